// round 14
// baseline (speedup 1.0000x reference)
#include <cuda_runtime.h>
#include <cuda_bf16.h>
#include <math.h>

// B=2, L=2048, H=8, DK=DV=64, D=512, KSZ=3, pad=1
#define NROWS 32768            // B*H*L
#define BH    16               // B*H
#define LSEQ  2048
#define DHEAD 64
#define DMOD  512
#define M4    4096             // B*L

// ---------------- device scratch -------------------------------------------
__device__ float g_vh[BH * LSEQ * DHEAD];
__device__ __align__(128) __nv_bfloat16 g_qs[3][BH * LSEQ * DHEAD];
__device__ __align__(128) __nv_bfloat16 g_ks[3][BH * LSEQ * DHEAD];
__device__ float g_eld[(size_t)BH * LSEQ * LSEQ];   // 268MB logits
__device__ float g_attnout[M4 * DMOD];
__device__ float g_fcout[M4 * DMOD];
__device__ float g_dtab[4095];
__device__ unsigned int g_tilemax_u[NROWS * 16];    // per-(row, 128col-tile) max

// ---------------- helpers ----------------------------------------------------
__device__ __forceinline__ unsigned smem_u32(const void* p) {
    unsigned a;
    asm("{ .reg .u64 t; cvta.to.shared.u64 t, %1; cvt.u32.u64 %0, t; }" : "=r"(a) : "l"(p));
    return a;
}
__device__ __forceinline__ unsigned sw128(unsigned x) { return x ^ ((x >> 3) & 0x70); }

#define LDSM_X4(r0, r1, r2, r3, addr) \
    asm volatile("ldmatrix.sync.aligned.m8n8.x4.shared.b16 {%0,%1,%2,%3}, [%4];" \
                 : "=r"(r0), "=r"(r1), "=r"(r2), "=r"(r3) : "r"(addr))

#define MMA16816(d, a, b) \
    asm volatile("mma.sync.aligned.m16n8k16.row.col.f32.bf16.bf16.f32 " \
                 "{%0,%1,%2,%3}, {%4,%5,%6,%7}, {%8,%9}, {%0,%1,%2,%3};" \
                 : "+f"((d)[0]), "+f"((d)[1]), "+f"((d)[2]), "+f"((d)[3]) \
                 : "r"((a)[0]), "r"((a)[1]), "r"((a)[2]), "r"((a)[3]), \
                   "r"((b)[0]), "r"((b)[1]))

#define CP16(dst, src) \
    asm volatile("cp.async.cg.shared.global [%0], [%1], 16;" :: "r"(dst), "l"(src))
#define CP_COMMIT() asm volatile("cp.async.commit_group;" ::: "memory")
#define CP_WAIT(n)  asm volatile("cp.async.wait_group %0;" :: "n"(n) : "memory")

extern __shared__ char dsmem[];

// ---------------- shared HMMA inner machinery --------------------------------
template <int NS>
__device__ __forceinline__ void mma_chunk(unsigned sbA, unsigned sbB,
                                          int wr, int wc, int sub, int l7,
                                          float acc[2][8][4]) {
#pragma unroll
    for (int ks = 0; ks < 4; ks++) {
        int kb = ks * 32;
        unsigned afr[NS][2][4];
#pragma unroll
        for (int s = 0; s < NS; s++)
#pragma unroll
            for (int mi = 0; mi < 2; mi++) {
                int r = wr * 32 + mi * 16 + l7 + (sub & 1) * 8;
                int byt = kb + (sub >> 1) * 16;
                unsigned ad = sbA + s * 16384 + sw128((unsigned)(r * 128 + byt));
                LDSM_X4(afr[s][mi][0], afr[s][mi][1], afr[s][mi][2], afr[s][mi][3], ad);
            }
#pragma unroll
        for (int s = 0; s < NS; s++) {
            unsigned bfr[8][2];
#pragma unroll
            for (int np = 0; np < 4; np++) {
                int n = wc * 64 + np * 16 + l7 + (sub >> 1) * 8;
                int byt = kb + (sub & 1) * 16;
                unsigned bd = sbB + s * 16384 + sw128((unsigned)(n * 128 + byt));
                unsigned r0, r1, r2, r3;
                LDSM_X4(r0, r1, r2, r3, bd);
                bfr[np * 2][0] = r0; bfr[np * 2][1] = r1;
                bfr[np * 2 + 1][0] = r2; bfr[np * 2 + 1][1] = r3;
            }
#pragma unroll
            for (int a = 0; a < NS - s; a++)
#pragma unroll
                for (int mi = 0; mi < 2; mi++)
#pragma unroll
                    for (int ni = 0; ni < 8; ni++)
                        MMA16816(acc[mi][ni], afr[a][mi], bfr[ni]);
        }
    }
}

template <int NS>
__device__ __forceinline__ void load_split_tile(const float* __restrict__ src,
                                                int row0, int kc, char* dst) {
    int tid = threadIdx.x;
#pragma unroll
    for (int p = 0; p < 8; p++) {
        int f = tid + p * 256;
        int r = f >> 4;
        int c4 = (f & 15) << 2;
        float4 v = *(const float4*)(src + (size_t)(row0 + r) * 512 + kc + c4);
        float xs[4] = {v.x, v.y, v.z, v.w};
        union { __nv_bfloat16 h[4]; uint2 u; } pk[NS];
#pragma unroll
        for (int u = 0; u < 4; u++) {
            float x = xs[u];
#pragma unroll
            for (int s = 0; s < NS; s++) {
                __nv_bfloat16 b = __float2bfloat16(x);
                pk[s].h[u] = b;
                x -= __bfloat162float(b);
            }
        }
        unsigned off = sw128((unsigned)(r * 128 + c4 * 2));
#pragma unroll
        for (int s = 0; s < NS; s++)
            *(uint2*)(dst + s * 16384 + off) = pk[s].u;
    }
}

template <int NS>
__device__ __forceinline__ void gemm_core(const float* A, const float* W,
                                          unsigned sb, char* smp,
                                          float acc[2][8][4]) {
    int tid = threadIdx.x;
    int wid = tid >> 5, lane = tid & 31;
#pragma unroll 1
    for (int kc = 0; kc < 512; kc += 64) {
        __syncthreads();
        load_split_tile<NS>(A, blockIdx.y * 128, kc, smp);
        load_split_tile<NS>(W, blockIdx.x * 128, kc, smp + NS * 16384);
        __syncthreads();
        mma_chunk<NS>(sb, sb + NS * 16384, wid & 3, wid >> 2, lane >> 3, lane & 7, acc);
    }
}

__device__ __forceinline__ void stage_acc(float* stage, float acc[2][8][4],
                                          int wid, int lane) {
    int rbase = (wid & 3) * 32 + (lane >> 2);
    int cbase = (wid >> 2) * 64 + (lane & 3) * 2;
#pragma unroll
    for (int mi = 0; mi < 2; mi++)
#pragma unroll
        for (int ni = 0; ni < 8; ni++)
#pragma unroll
            for (int u = 0; u < 4; u++)
                stage[(rbase + mi * 16 + (u >> 1) * 8) * 132 +
                      cbase + ni * 8 + (u & 1)] = acc[mi][ni][u];
}

// fragment loaders for staged eld pipeline
__device__ __forceinline__ void ld_afrag(unsigned sbA, int s, int wr, int sub,
                                         int l7, int kb, unsigned out[2][4]) {
#pragma unroll
    for (int mi = 0; mi < 2; mi++) {
        int r = wr * 32 + mi * 16 + l7 + (sub & 1) * 8;
        int byt = kb + (sub >> 1) * 16;
        unsigned ad = sbA + s * 16384 + sw128((unsigned)(r * 128 + byt));
        LDSM_X4(out[mi][0], out[mi][1], out[mi][2], out[mi][3], ad);
    }
}
__device__ __forceinline__ void ld_bfrag(unsigned sbB, int s, int wc, int sub,
                                         int l7, int kb, unsigned bfr[8][2]) {
#pragma unroll
    for (int np = 0; np < 4; np++) {
        int n = wc * 64 + np * 16 + l7 + (sub >> 1) * 8;
        int byt = kb + (sub & 1) * 16;
        unsigned bd = sbB + s * 16384 + sw128((unsigned)(n * 128 + byt));
        unsigned r0, r1, r2, r3;
        LDSM_X4(r0, r1, r2, r3, bd);
        bfr[np * 2][0] = r0; bfr[np * 2][1] = r1;
        bfr[np * 2 + 1][0] = r2; bfr[np * 2 + 1][1] = r3;
    }
}
__device__ __forceinline__ void mma_all(float acc[2][8][4], unsigned a[2][4],
                                        unsigned b[8][2]) {
#pragma unroll
    for (int mi = 0; mi < 2; mi++)
#pragma unroll
        for (int ni = 0; ni < 8; ni++)
            MMA16816(acc[mi][ni], a[mi], b[ni]);
}

// stage 0: (0,0) ; stage 1: (1,0),(0,1),(1,1) ; stage 2: (2,0),(0,2)
template <int STAGE>
__device__ __forceinline__ void mma_stage(unsigned sbA, unsigned sbB,
                                          int wr, int wc, int sub, int l7,
                                          float acc[2][8][4]) {
#pragma unroll
    for (int ks = 0; ks < 4; ks++) {
        int kb = ks * 32;
        unsigned a0[2][4], ax[2][4], bfr[8][2];
        if (STAGE == 0) {
            ld_afrag(sbA, 0, wr, sub, l7, kb, a0);
            ld_bfrag(sbB, 0, wc, sub, l7, kb, bfr);
            mma_all(acc, a0, bfr);
        } else if (STAGE == 1) {
            ld_afrag(sbA, 0, wr, sub, l7, kb, a0);
            ld_afrag(sbA, 1, wr, sub, l7, kb, ax);
            ld_bfrag(sbB, 0, wc, sub, l7, kb, bfr);
            mma_all(acc, ax, bfr);                 // (1,0)
            ld_bfrag(sbB, 1, wc, sub, l7, kb, bfr);
            mma_all(acc, a0, bfr);                 // (0,1)
            mma_all(acc, ax, bfr);                 // (1,1)
        } else {
            ld_afrag(sbA, 0, wr, sub, l7, kb, a0);
            ld_afrag(sbA, 2, wr, sub, l7, kb, ax);
            ld_bfrag(sbB, 0, wc, sub, l7, kb, bfr);
            mma_all(acc, ax, bfr);                 // (2,0)
            ld_bfrag(sbB, 2, wc, sub, l7, kb, bfr);
            mma_all(acc, a0, bfr);                 // (0,2)
        }
    }
}

// ---------------- init ------------------------------------------------------
__global__ void k_init() {
    int t = blockIdx.x * blockDim.x + threadIdx.x;
    if (t < 4095) {
        double alpha = -log(0.001 / 7.0 * 3.0);   // ALPHA_C
        g_dtab[t] = (float)(-alpha * (double)(t - 2047));
    }
    if (t < NROWS * 16) g_tilemax_u[t] = 0u;
}

// ---------------- fused q/k/v projection (single launch) ---------------------
__global__ void __launch_bounds__(256, 2) k_proj_all(
        const float* __restrict__ qi, const float* __restrict__ ki,
        const float* __restrict__ vi, const float* __restrict__ wq,
        const float* __restrict__ wk, const float* __restrict__ wv) {
    int z = blockIdx.z;
    int tid = threadIdx.x;
    int wid = tid >> 5, lane = tid & 31;

    unsigned raw = smem_u32(dsmem);
    unsigned sb = (raw + 1023) & ~1023u;
    char* smp = dsmem + (sb - raw);

    float acc[2][8][4];
#pragma unroll
    for (int mi = 0; mi < 2; mi++)
#pragma unroll
        for (int ni = 0; ni < 8; ni++)
#pragma unroll
            for (int u = 0; u < 4; u++) acc[mi][ni][u] = 0.f;

    if (z == 2) {
        gemm_core<2>(vi, wv, sb, smp, acc);
    } else {
        gemm_core<3>(z ? ki : qi, z ? wk : wq, sb, smp, acc);
    }

    __syncthreads();
    float* stage = (float*)smp;
    stage_acc(stage, acc, wid, lane);
    __syncthreads();

    int m0 = blockIdx.y * 128, n0 = blockIdx.x * 128;
    if (z == 2) {
#pragma unroll
        for (int p = 0; p < 16; p++) {
            int f = tid + p * 256;
            int r = f >> 5, q = f & 31;
            int m = m0 + r, bb = m >> 11, l = m & 2047;
            int n = n0 + q * 4, h = n >> 6, dk = n & 63;
            float4 v = *(const float4*)(stage + r * 132 + q * 4);
            *(float4*)(g_vh + ((size_t)(bb * 8 + h) * LSEQ + l) * 64 + dk) = v;
        }
    } else {
        __nv_bfloat16* S0 = z ? g_ks[0] : g_qs[0];
        __nv_bfloat16* S1 = z ? g_ks[1] : g_qs[1];
        __nv_bfloat16* S2 = z ? g_ks[2] : g_qs[2];
#pragma unroll
        for (int p = 0; p < 16; p++) {
            int f = tid + p * 256;
            int r = f >> 5, q = f & 31;
            int m = m0 + r, bb = m >> 11, l = m & 2047;
            int n = n0 + q * 4, h = n >> 6, dk = n & 63;
            float4 v = *(const float4*)(stage + r * 132 + q * 4);
            float xs[4] = {v.x, v.y, v.z, v.w};
            union { __nv_bfloat16 h4[4]; uint2 u; } p0, p1, p2;
#pragma unroll
            for (int u = 0; u < 4; u++) {
                float x = xs[u];
                __nv_bfloat16 b0 = __float2bfloat16(x);
                float r1 = x - __bfloat162float(b0);
                __nv_bfloat16 b1 = __float2bfloat16(r1);
                float r2 = r1 - __bfloat162float(b1);
                __nv_bfloat16 b2 = __float2bfloat16(r2);
                p0.h4[u] = b0; p1.h4[u] = b1; p2.h4[u] = b2;
            }
            size_t off = ((size_t)(bb * 8 + h) * LSEQ + l) * 64 + dk;
            *(uint2*)(S0 + off) = p0.u;
            *(uint2*)(S1 + off) = p1.u;
            *(uint2*)(S2 + off) = p2.u;
        }
    }
}

// ---------------- fc projection (bf16x2, 3 products) ------------------------
__global__ void __launch_bounds__(256, 2) k_fc2(const float* __restrict__ wfc) {
    int tid = threadIdx.x;
    int wid = tid >> 5, lane = tid & 31;
    unsigned raw = smem_u32(dsmem);
    unsigned sb = (raw + 1023) & ~1023u;
    char* smp = dsmem + (sb - raw);

    float acc[2][8][4];
#pragma unroll
    for (int mi = 0; mi < 2; mi++)
#pragma unroll
        for (int ni = 0; ni < 8; ni++)
#pragma unroll
            for (int u = 0; u < 4; u++) acc[mi][ni][u] = 0.f;

    gemm_core<2>(g_attnout, wfc, sb, smp, acc);

    __syncthreads();
    float* stage = (float*)smp;
    stage_acc(stage, acc, wid, lane);
    __syncthreads();

    int m0 = blockIdx.y * 128, n0 = blockIdx.x * 128;
#pragma unroll
    for (int p = 0; p < 16; p++) {
        int f = tid + p * 256;
        int r = f >> 5, q = f & 31;
        float4 v = *(const float4*)(stage + r * 132 + q * 4);
        *(float4*)(g_fcout + (size_t)(m0 + r) * 512 + n0 + q * 4) = v;
    }
}

// ---------------- eld logits: pipelined HMMA bf16x3 + per-tile max ----------
__global__ void __launch_bounds__(256, 2) k_eld_mma() {
    int tid = threadIdx.x;
    int wid = tid >> 5, lane = tid & 31;
    int bh = blockIdx.z;
    int i0 = blockIdx.y * 128, j0 = blockIdx.x * 128;

    unsigned raw = smem_u32(dsmem);
    unsigned sb = (raw + 1023) & ~1023u;
    char* smp = dsmem + (sb - raw);

    size_t rbq = ((size_t)bh * LSEQ + i0) * 64;
    size_t rbk = ((size_t)bh * LSEQ + j0) * 64;
#pragma unroll
    for (int s = 0; s < 3; s++) {
        const char* qsrc = (const char*)(g_qs[s] + rbq);
        const char* ksrc = (const char*)(g_ks[s] + rbk);
#pragma unroll
        for (int p = 0; p < 4; p++) {
            int f = tid + p * 256;
            int r = f >> 3;
            int cb = (f & 7) * 16;
            unsigned off = sw128(r * 128 + cb);
            CP16(sb + s * 16384 + off, qsrc + r * 128 + cb);
            CP16(sb + 49152 + s * 16384 + off, ksrc + r * 128 + cb);
        }
        CP_COMMIT();
    }

    float acc[2][8][4];
#pragma unroll
    for (int mi = 0; mi < 2; mi++)
#pragma unroll
        for (int ni = 0; ni < 8; ni++)
#pragma unroll
            for (int u = 0; u < 4; u++) acc[mi][ni][u] = 0.f;

    int wr = wid & 3, wc = wid >> 2, sub = lane >> 3, l7 = lane & 7;

    CP_WAIT(2); __syncthreads();
    mma_stage<0>(sb, sb + 49152, wr, wc, sub, l7, acc);
    CP_WAIT(1); __syncthreads();
    mma_stage<1>(sb, sb + 49152, wr, wc, sub, l7, acc);
    CP_WAIT(0); __syncthreads();
    mma_stage<2>(sb, sb + 49152, wr, wc, sub, l7, acc);
    __syncthreads();

    float* stage = (float*)smp;
    int rbase = wr * 32 + (lane >> 2);
    int cbase = wc * 64 + (lane & 3) * 2;
    float mx[2][2] = {{-INFINITY, -INFINITY}, {-INFINITY, -INFINITY}};
#pragma unroll
    for (int mi = 0; mi < 2; mi++) {
#pragma unroll
        for (int ni = 0; ni < 8; ni++) {
#pragma unroll
            for (int u = 0; u < 4; u++) {
                int rloc = rbase + mi * 16 + (u >> 1) * 8;
                int cloc = cbase + ni * 8 + (u & 1);
                int i = i0 + rloc, j = j0 + cloc;
                float e = g_dtab[j - i + 2047] * (acc[mi][ni][u] * 0.125f);
                stage[rloc * 132 + cloc] = e;
                mx[mi][u >> 1] = fmaxf(mx[mi][u >> 1], e);
            }
        }
    }
#pragma unroll
    for (int mi = 0; mi < 2; mi++)
#pragma unroll
        for (int hh = 0; hh < 2; hh++) {
            float r = mx[mi][hh];
            r = fmaxf(r, __shfl_xor_sync(0xffffffffu, r, 1));
            r = fmaxf(r, __shfl_xor_sync(0xffffffffu, r, 2));
            if ((lane & 3) == 0) {
                int i = i0 + rbase + mi * 16 + hh * 8;
                unsigned u = __float_as_uint(r);
                unsigned key = (u & 0x80000000u) ? ~u : (u | 0x80000000u);
                atomicMax(&g_tilemax_u[(bh * LSEQ + i) * 16 + blockIdx.x], key);
            }
        }
    __syncthreads();

    float* erow = g_eld + ((size_t)bh * LSEQ + i0) * LSEQ + j0;
#pragma unroll
    for (int p = 0; p < 16; p++) {
        int f = tid + p * 256;
        int r = f >> 5, q = f & 31;
        float4 v = *(const float4*)(stage + r * 132 + q * 4);
        *(float4*)(erow + (size_t)r * LSEQ + q * 4) = v;
    }
}

// ---------------- warp-per-row softmax + pool + batched PV ------------------
// smem: p_w 8x2048 f32 (64KB) | mC 8x64 u32 (2KB) | cpos 8x128 u16 (2KB)
#define RCAP 128
__global__ void __launch_bounds__(256) k_row6(float* __restrict__ pooled_out) {
    extern __shared__ char rsm[];
    int tid = threadIdx.x, wid = tid >> 5, lane = tid & 31;
    float* p_w = (float*)rsm + wid * 2048;
    unsigned* mC = (unsigned*)(rsm + 65536) + wid * 64;
    unsigned short* cpos_w = (unsigned short*)(rsm + 67584) + wid * RCAP;

    int row = blockIdx.x * 8 + wid;
    int bh = row >> 11;
    int i  = row & 2047;
    int b  = bh >> 3, h = bh & 7;

    float tm = -INFINITY;
    if (lane < 16) {
        unsigned kk = g_tilemax_u[row * 16 + lane];
        unsigned ub = (kk & 0x80000000u) ? (kk ^ 0x80000000u) : ~kk;
        tm = __uint_as_float(ub);
    }
    float mx = tm;
#pragma unroll
    for (int o = 16; o > 0; o >>= 1)
        mx = fmaxf(mx, __shfl_xor_sync(0xffffffffu, mx, o));
    unsigned nd = __ballot_sync(0xffffffffu, tm > mx - 88.0f) & 0xffffu;

    mC[lane] = 0u; mC[lane + 32] = 0u;
    unsigned ti = nd;
    while (ti) {
        int t = __ffs(ti) - 1; ti &= ti - 1;
        *(float4*)(p_w + t * 128 + lane * 4) = make_float4(0.f, 0.f, 0.f, 0.f);
    }
    __syncwarp();

    const float* eldrow = g_eld + (size_t)row * LSEQ;
    float lsum = 0.f;
    ti = nd;
    while (ti) {
        int t = __ffs(ti) - 1; ti &= ti - 1;
        int pos = t * 128 + lane * 4;
        float4 e = *(const float4*)(eldrow + pos);
        float ev[4] = {e.x, e.y, e.z, e.w};
#pragma unroll
        for (int u = 0; u < 4; u++) {
            float arg = ev[u] - mx;
            if (arg > -88.0f) {
                float ex = expf(arg);
                p_w[pos + u] = ex;
                lsum += ex;
                int pp0 = pos + u;
                int lo = (pp0 > 0) ? pp0 - 1 : 0;
                int hi = (pp0 < 2047) ? pp0 + 1 : 2047;
                for (int pp = lo; pp <= hi; pp++)
                    atomicOr(&mC[pp >> 5], 1u << (pp & 31));
            }
        }
    }
    __syncwarp();
#pragma unroll
    for (int o = 16; o > 0; o >>= 1)
        lsum += __shfl_xor_sync(0xffffffffu, lsum, o);
    float S = lsum;

    ti = nd;
    while (ti) {
        int t = __ffs(ti) - 1; ti &= ti - 1;
        int pos = t * 128 + lane * 4;
        float4 pv = *(const float4*)(p_w + pos);
        pv.x /= S; pv.y /= S; pv.z /= S; pv.w /= S;
        *(float4*)(p_w + pos) = pv;
    }
    __syncwarp();

#define PVAL(pos) (((nd >> ((pos) >> 7)) & 1u) ? p_w[(pos)] : 0.f)

    // candidate position list (lane-major = globally ascending)
    unsigned w0 = mC[lane * 2], w1 = mC[lane * 2 + 1];
    int cnt = __popc(w0) + __popc(w1);
    int incl = cnt;
#pragma unroll
    for (int o = 1; o < 32; o <<= 1) {
        int t = __shfl_up_sync(0xffffffffu, incl, o);
        if (lane >= o) incl += t;
    }
    int basei = incl - cnt;
    int total = __shfl_sync(0xffffffffu, incl, 31);
    {
        int idx = basei;
#pragma unroll
        for (int half = 0; half < 2; half++) {
            unsigned bw = half ? w1 : w0;
            int pbase = lane * 64 + half * 32;
            while (bw) {
                int bp = __ffs((int)bw) - 1;
                bw &= (bw - 1);
                if (idx < RCAP) cpos_w[idx] = (unsigned short)(pbase + bp);
                idx++;
            }
        }
    }
    __syncwarp();
    int cn = (total < RCAP) ? total : RCAP;

    // dense pooled write
    float* prow = pooled_out + (size_t)row * LSEQ;
#pragma unroll 1
    for (int o = 0; o < 16; o++) {
        int pos = o * 128 + lane * 4;
        unsigned bits = (mC[pos >> 5] >> (pos & 31)) & 0xFu;
        float out4[4] = {0.f, 0.f, 0.f, 0.f};
        if (bits) {
#pragma unroll
            for (int u = 0; u < 4; u++) {
                if (bits & (1u << u)) {
                    int p = pos + u;
                    float pm = (p > 0)    ? PVAL(p - 1) : 0.f;
                    float pz = PVAL(p);
                    float pq = (p < 2047) ? PVAL(p + 1) : 0.f;
                    out4[u] = ((pm + pz) + pq) / 3.0f;
                }
            }
        }
        *(float4*)(prow + pos) = make_float4(out4[0], out4[1], out4[2], out4[3]);
    }

    // batched PV: 8 candidates/batch; pooled vals recomputed from p_w
    {
        const float* vb = g_vh + (size_t)bh * LSEQ * 64;
        float a0 = 0.f, a1 = 0.f;
#pragma unroll 1
        for (int c0 = 0; c0 < cn; c0 += 8) {
            int nb = cn - c0; if (nb > 8) nb = 8;
            float vl[8], va[8], vq[8];
#pragma unroll
            for (int bq = 0; bq < 8; bq++) {
                if (bq < nb) {
                    int p = cpos_w[c0 + bq];
                    float pm = (p > 0)    ? PVAL(p - 1) : 0.f;
                    float pz = PVAL(p);
                    float pq = (p < 2047) ? PVAL(p + 1) : 0.f;
                    vl[bq] = ((pm + pz) + pq) / 3.0f;
                    const float* vr = vb + (size_t)p * 64;
                    va[bq] = vr[lane];
                    vq[bq] = vr[lane + 32];
                } else { vl[bq] = 0.f; va[bq] = 0.f; vq[bq] = 0.f; }
            }
#pragma unroll
            for (int bq = 0; bq < 8; bq++) {
                a0 = fmaf(vl[bq], va[bq], a0);
                a1 = fmaf(vl[bq], vq[bq], a1);
            }
        }
        float* ob = g_attnout + ((size_t)(b * LSEQ + i)) * DMOD + h * 64;
        ob[lane] = a0;
        ob[lane + 32] = a1;
    }
#undef PVAL
}

// ---------------- residual + LayerNorm --------------------------------------
__global__ void k_ln(const float* __restrict__ resid, const float* __restrict__ gamma,
                     const float* __restrict__ beta, float* __restrict__ outp) {
    __shared__ float red[128];
    int m = blockIdx.x;
    int tid = threadIdx.x;
    float4 f = *(const float4*)(g_fcout + (size_t)m * 512 + tid * 4);
    float4 r = *(const float4*)(resid + (size_t)m * 512 + tid * 4);
    float y[4] = {f.x + r.x, f.y + r.y, f.z + r.z, f.w + r.w};

    float s = (y[0] + y[1]) + (y[2] + y[3]);
    red[tid] = s;
    __syncthreads();
    for (int st = 64; st > 0; st >>= 1) {
        if (tid < st) red[tid] += red[tid + st];
        __syncthreads();
    }
    float mu = red[0] * (1.0f / 512.0f);
    __syncthreads();

    float d[4] = {y[0] - mu, y[1] - mu, y[2] - mu, y[3] - mu};
    float sq = (d[0] * d[0] + d[1] * d[1]) + (d[2] * d[2] + d[3] * d[3]);
    red[tid] = sq;
    __syncthreads();
    for (int st = 64; st > 0; st >>= 1) {
        if (tid < st) red[tid] += red[tid + st];
        __syncthreads();
    }
    float var = red[0] * (1.0f / 512.0f);
    float inv = 1.0f / sqrtf(var + 1e-6f);

    float4 g = *(const float4*)(gamma + tid * 4);
    float4 bb = *(const float4*)(beta + tid * 4);
    float4 o = make_float4(d[0] * inv * g.x + bb.x, d[1] * inv * g.y + bb.y,
                           d[2] * inv * g.z + bb.z, d[3] * inv * g.w + bb.w);
    *(float4*)(outp + (size_t)m * 512 + tid * 4) = o;
}

// ---------------- launch -----------------------------------------------------
#define SMEM3 (98304 + 1024)
#define SMEM2 (67584 + 1024)
#define SMEMR (65536 + 2048 + 2048)

extern "C" void kernel_launch(void* const* d_in, const int* in_sizes, int n_in,
                              void* d_out, int out_size) {
    const float* q     = (const float*)d_in[0];
    const float* k     = (const float*)d_in[1];
    const float* v     = (const float*)d_in[2];
    const float* wq    = (const float*)d_in[3];
    const float* wk    = (const float*)d_in[4];
    const float* wv    = (const float*)d_in[5];
    const float* wfc   = (const float*)d_in[6];
    const float* gamma = (const float*)d_in[7];
    const float* beta  = (const float*)d_in[8];

    float* outp = (float*)d_out;            // [B,L,1,D]
    float* pooledp = outp + 2097152;        // [B,H,L,L]

    cudaFuncSetAttribute(k_proj_all, cudaFuncAttributeMaxDynamicSharedMemorySize, SMEM3);
    cudaFuncSetAttribute(k_fc2,      cudaFuncAttributeMaxDynamicSharedMemorySize, SMEM2);
    cudaFuncSetAttribute(k_eld_mma,  cudaFuncAttributeMaxDynamicSharedMemorySize, SMEM3);
    cudaFuncSetAttribute(k_row6,     cudaFuncAttributeMaxDynamicSharedMemorySize, SMEMR);

    k_init<<<2048, 256>>>();
    k_proj_all<<<dim3(4, 32, 3), 256, SMEM3>>>(q, k, v, wq, wk, wv);
    k_eld_mma<<<dim3(16, 16, 16), 256, SMEM3>>>();
    k_row6<<<4096, 256, SMEMR>>>(pooledp);
    k_fc2<<<dim3(4, 32), 256, SMEM2>>>(wfc);
    k_ln<<<4096, 128>>>(q, gamma, beta, outp);
}

// round 15
// speedup vs baseline: 1.0372x; 1.0372x over previous
#include <cuda_runtime.h>
#include <cuda_bf16.h>
#include <math.h>

// B=2, L=2048, H=8, DK=DV=64, D=512, KSZ=3, pad=1
#define NROWS 32768            // B*H*L
#define BH    16               // B*H
#define LSEQ  2048
#define DHEAD 64
#define DMOD  512
#define M4    4096             // B*L

// ---------------- device scratch -------------------------------------------
__device__ float g_vh[BH * LSEQ * DHEAD];
__device__ __align__(128) __nv_bfloat16 g_qs[3][BH * LSEQ * DHEAD];
__device__ __align__(128) __nv_bfloat16 g_ks[3][BH * LSEQ * DHEAD];
__device__ float g_eld[(size_t)BH * LSEQ * LSEQ];   // 268MB logits
__device__ float g_attnout[M4 * DMOD];
__device__ float g_fcout[M4 * DMOD];
__device__ float g_fcout2[M4 * DMOD];
__device__ float g_dtab[4095];
__device__ unsigned int g_tilemax_u[NROWS * 16];    // per-(row, 128col-tile) max

// ---------------- helpers ----------------------------------------------------
__device__ __forceinline__ unsigned smem_u32(const void* p) {
    unsigned a;
    asm("{ .reg .u64 t; cvta.to.shared.u64 t, %1; cvt.u32.u64 %0, t; }" : "=r"(a) : "l"(p));
    return a;
}
__device__ __forceinline__ unsigned sw128(unsigned x) { return x ^ ((x >> 3) & 0x70); }

#define LDSM_X4(r0, r1, r2, r3, addr) \
    asm volatile("ldmatrix.sync.aligned.m8n8.x4.shared.b16 {%0,%1,%2,%3}, [%4];" \
                 : "=r"(r0), "=r"(r1), "=r"(r2), "=r"(r3) : "r"(addr))

#define MMA16816(d, a, b) \
    asm volatile("mma.sync.aligned.m16n8k16.row.col.f32.bf16.bf16.f32 " \
                 "{%0,%1,%2,%3}, {%4,%5,%6,%7}, {%8,%9}, {%0,%1,%2,%3};" \
                 : "+f"((d)[0]), "+f"((d)[1]), "+f"((d)[2]), "+f"((d)[3]) \
                 : "r"((a)[0]), "r"((a)[1]), "r"((a)[2]), "r"((a)[3]), \
                   "r"((b)[0]), "r"((b)[1]))

#define CP16(dst, src) \
    asm volatile("cp.async.cg.shared.global [%0], [%1], 16;" :: "r"(dst), "l"(src))
#define CP_COMMIT() asm volatile("cp.async.commit_group;" ::: "memory")
#define CP_WAIT(n)  asm volatile("cp.async.wait_group %0;" :: "n"(n) : "memory")

extern __shared__ char dsmem[];

// ---------------- shared HMMA inner machinery --------------------------------
template <int NS>
__device__ __forceinline__ void mma_chunk(unsigned sbA, unsigned sbB,
                                          int wr, int wc, int sub, int l7,
                                          float acc[2][8][4]) {
#pragma unroll
    for (int ks = 0; ks < 4; ks++) {
        int kb = ks * 32;
        unsigned afr[NS][2][4];
#pragma unroll
        for (int s = 0; s < NS; s++)
#pragma unroll
            for (int mi = 0; mi < 2; mi++) {
                int r = wr * 32 + mi * 16 + l7 + (sub & 1) * 8;
                int byt = kb + (sub >> 1) * 16;
                unsigned ad = sbA + s * 16384 + sw128((unsigned)(r * 128 + byt));
                LDSM_X4(afr[s][mi][0], afr[s][mi][1], afr[s][mi][2], afr[s][mi][3], ad);
            }
#pragma unroll
        for (int s = 0; s < NS; s++) {
            unsigned bfr[8][2];
#pragma unroll
            for (int np = 0; np < 4; np++) {
                int n = wc * 64 + np * 16 + l7 + (sub >> 1) * 8;
                int byt = kb + (sub & 1) * 16;
                unsigned bd = sbB + s * 16384 + sw128((unsigned)(n * 128 + byt));
                unsigned r0, r1, r2, r3;
                LDSM_X4(r0, r1, r2, r3, bd);
                bfr[np * 2][0] = r0; bfr[np * 2][1] = r1;
                bfr[np * 2 + 1][0] = r2; bfr[np * 2 + 1][1] = r3;
            }
#pragma unroll
            for (int a = 0; a < NS - s; a++)
#pragma unroll
                for (int mi = 0; mi < 2; mi++)
#pragma unroll
                    for (int ni = 0; ni < 8; ni++)
                        MMA16816(acc[mi][ni], afr[a][mi], bfr[ni]);
        }
    }
}

template <int NS>
__device__ __forceinline__ void load_split_tile(const float* __restrict__ src,
                                                int row0, int kc, char* dst) {
    int tid = threadIdx.x;
#pragma unroll
    for (int p = 0; p < 8; p++) {
        int f = tid + p * 256;
        int r = f >> 4;
        int c4 = (f & 15) << 2;
        float4 v = *(const float4*)(src + (size_t)(row0 + r) * 512 + kc + c4);
        float xs[4] = {v.x, v.y, v.z, v.w};
        union { __nv_bfloat16 h[4]; uint2 u; } pk[NS];
#pragma unroll
        for (int u = 0; u < 4; u++) {
            float x = xs[u];
#pragma unroll
            for (int s = 0; s < NS; s++) {
                __nv_bfloat16 b = __float2bfloat16(x);
                pk[s].h[u] = b;
                x -= __bfloat162float(b);
            }
        }
        unsigned off = sw128((unsigned)(r * 128 + c4 * 2));
#pragma unroll
        for (int s = 0; s < NS; s++)
            *(uint2*)(dst + s * 16384 + off) = pk[s].u;
    }
}

template <int NS>
__device__ __forceinline__ void gemm_core(const float* A, const float* W,
                                          unsigned sb, char* smp,
                                          float acc[2][8][4],
                                          int kbeg, int kend) {
    int tid = threadIdx.x;
    int wid = tid >> 5, lane = tid & 31;
#pragma unroll 1
    for (int kc = kbeg; kc < kend; kc += 64) {
        __syncthreads();
        load_split_tile<NS>(A, blockIdx.y * 128, kc, smp);
        load_split_tile<NS>(W, blockIdx.x * 128, kc, smp + NS * 16384);
        __syncthreads();
        mma_chunk<NS>(sb, sb + NS * 16384, wid & 3, wid >> 2, lane >> 3, lane & 7, acc);
    }
}

__device__ __forceinline__ void stage_acc(float* stage, float acc[2][8][4],
                                          int wid, int lane) {
    int rbase = (wid & 3) * 32 + (lane >> 2);
    int cbase = (wid >> 2) * 64 + (lane & 3) * 2;
#pragma unroll
    for (int mi = 0; mi < 2; mi++)
#pragma unroll
        for (int ni = 0; ni < 8; ni++)
#pragma unroll
            for (int u = 0; u < 4; u++)
                stage[(rbase + mi * 16 + (u >> 1) * 8) * 132 +
                      cbase + ni * 8 + (u & 1)] = acc[mi][ni][u];
}

// fragment loaders with explicit buffer base
__device__ __forceinline__ void ld_afragB(unsigned abuf, int wr, int sub,
                                          int l7, int kb, unsigned out[2][4]) {
#pragma unroll
    for (int mi = 0; mi < 2; mi++) {
        int r = wr * 32 + mi * 16 + l7 + (sub & 1) * 8;
        int byt = kb + (sub >> 1) * 16;
        unsigned ad = abuf + sw128((unsigned)(r * 128 + byt));
        LDSM_X4(out[mi][0], out[mi][1], out[mi][2], out[mi][3], ad);
    }
}
__device__ __forceinline__ void ld_bfragB(unsigned bbuf, int wc, int sub,
                                          int l7, int kb, unsigned bfr[8][2]) {
#pragma unroll
    for (int np = 0; np < 4; np++) {
        int n = wc * 64 + np * 16 + l7 + (sub >> 1) * 8;
        int byt = kb + (sub & 1) * 16;
        unsigned bd = bbuf + sw128((unsigned)(n * 128 + byt));
        unsigned r0, r1, r2, r3;
        LDSM_X4(r0, r1, r2, r3, bd);
        bfr[np * 2][0] = r0; bfr[np * 2][1] = r1;
        bfr[np * 2 + 1][0] = r2; bfr[np * 2 + 1][1] = r3;
    }
}
__device__ __forceinline__ void mma_all(float acc[2][8][4], unsigned a[2][4],
                                        unsigned b[8][2]) {
#pragma unroll
    for (int mi = 0; mi < 2; mi++)
#pragma unroll
        for (int ni = 0; ni < 8; ni++)
            MMA16816(acc[mi][ni], a[mi], b[ni]);
}

// ---------------- init ------------------------------------------------------
__global__ void k_init() {
    int t = blockIdx.x * blockDim.x + threadIdx.x;
    if (t < 4095) {
        double alpha = -log(0.001 / 7.0 * 3.0);   // ALPHA_C
        g_dtab[t] = (float)(-alpha * (double)(t - 2047));
    }
    if (t < NROWS * 16) g_tilemax_u[t] = 0u;
}

// ---------------- fused q/k/v projection (single launch) ---------------------
__global__ void __launch_bounds__(256, 2) k_proj_all(
        const float* __restrict__ qi, const float* __restrict__ ki,
        const float* __restrict__ vi, const float* __restrict__ wq,
        const float* __restrict__ wk, const float* __restrict__ wv) {
    int z = blockIdx.z;
    int tid = threadIdx.x;
    int wid = tid >> 5, lane = tid & 31;

    unsigned raw = smem_u32(dsmem);
    unsigned sb = (raw + 1023) & ~1023u;
    char* smp = dsmem + (sb - raw);

    float acc[2][8][4];
#pragma unroll
    for (int mi = 0; mi < 2; mi++)
#pragma unroll
        for (int ni = 0; ni < 8; ni++)
#pragma unroll
            for (int u = 0; u < 4; u++) acc[mi][ni][u] = 0.f;

    if (z == 2) {
        gemm_core<2>(vi, wv, sb, smp, acc, 0, 512);
    } else {
        gemm_core<3>(z ? ki : qi, z ? wk : wq, sb, smp, acc, 0, 512);
    }

    __syncthreads();
    float* stage = (float*)smp;
    stage_acc(stage, acc, wid, lane);
    __syncthreads();

    int m0 = blockIdx.y * 128, n0 = blockIdx.x * 128;
    if (z == 2) {
#pragma unroll
        for (int p = 0; p < 16; p++) {
            int f = tid + p * 256;
            int r = f >> 5, q = f & 31;
            int m = m0 + r, bb = m >> 11, l = m & 2047;
            int n = n0 + q * 4, h = n >> 6, dk = n & 63;
            float4 v = *(const float4*)(stage + r * 132 + q * 4);
            *(float4*)(g_vh + ((size_t)(bb * 8 + h) * LSEQ + l) * 64 + dk) = v;
        }
    } else {
        __nv_bfloat16* S0 = z ? g_ks[0] : g_qs[0];
        __nv_bfloat16* S1 = z ? g_ks[1] : g_qs[1];
        __nv_bfloat16* S2 = z ? g_ks[2] : g_qs[2];
#pragma unroll
        for (int p = 0; p < 16; p++) {
            int f = tid + p * 256;
            int r = f >> 5, q = f & 31;
            int m = m0 + r, bb = m >> 11, l = m & 2047;
            int n = n0 + q * 4, h = n >> 6, dk = n & 63;
            float4 v = *(const float4*)(stage + r * 132 + q * 4);
            float xs[4] = {v.x, v.y, v.z, v.w};
            union { __nv_bfloat16 h4[4]; uint2 u; } p0, p1, p2;
#pragma unroll
            for (int u = 0; u < 4; u++) {
                float x = xs[u];
                __nv_bfloat16 b0 = __float2bfloat16(x);
                float r1 = x - __bfloat162float(b0);
                __nv_bfloat16 b1 = __float2bfloat16(r1);
                float r2 = r1 - __bfloat162float(b1);
                __nv_bfloat16 b2 = __float2bfloat16(r2);
                p0.h4[u] = b0; p1.h4[u] = b1; p2.h4[u] = b2;
            }
            size_t off = ((size_t)(bb * 8 + h) * LSEQ + l) * 64 + dk;
            *(uint2*)(S0 + off) = p0.u;
            *(uint2*)(S1 + off) = p1.u;
            *(uint2*)(S2 + off) = p2.u;
        }
    }
}

// ---------------- fc projection: split-K halves ------------------------------
__global__ void __launch_bounds__(256, 2) k_fc2(const float* __restrict__ wfc) {
    int tid = threadIdx.x;
    int wid = tid >> 5, lane = tid & 31;
    unsigned raw = smem_u32(dsmem);
    unsigned sb = (raw + 1023) & ~1023u;
    char* smp = dsmem + (sb - raw);

    float acc[2][8][4];
#pragma unroll
    for (int mi = 0; mi < 2; mi++)
#pragma unroll
        for (int ni = 0; ni < 8; ni++)
#pragma unroll
            for (int u = 0; u < 4; u++) acc[mi][ni][u] = 0.f;

    int kh = blockIdx.z;   // 0 or 1
    gemm_core<2>(g_attnout, wfc, sb, smp, acc, kh * 256, kh * 256 + 256);

    __syncthreads();
    float* stage = (float*)smp;
    stage_acc(stage, acc, wid, lane);
    __syncthreads();

    float* dst = kh ? g_fcout2 : g_fcout;
    int m0 = blockIdx.y * 128, n0 = blockIdx.x * 128;
#pragma unroll
    for (int p = 0; p < 16; p++) {
        int f = tid + p * 256;
        int r = f >> 5, q = f & 31;
        float4 v = *(const float4*)(stage + r * 132 + q * 4);
        *(float4*)(dst + (size_t)(m0 + r) * 512 + n0 + q * 4) = v;
    }
}

// ---------------- eld logits: pipelined HMMA bf16x3, direct store -----------
// smem: q0 @0, k0 @16K, qx @32K, kx @48K  (splits 1 then 2 share qx/kx)
__global__ void __launch_bounds__(256, 2) k_eld_mma() {
    int tid = threadIdx.x;
    int wid = tid >> 5, lane = tid & 31;
    int bh = blockIdx.z;
    int i0 = blockIdx.y * 128, j0 = blockIdx.x * 128;

    unsigned raw = smem_u32(dsmem);
    unsigned sb = (raw + 1023) & ~1023u;

    size_t rbq = ((size_t)bh * LSEQ + i0) * 64;
    size_t rbk = ((size_t)bh * LSEQ + j0) * 64;

    // group 0: q0,k0 ; group 1: q1,k1 (into qx,kx)
#pragma unroll
    for (int g = 0; g < 2; g++) {
        const char* qsrc = (const char*)(g_qs[g] + rbq);
        const char* ksrc = (const char*)(g_ks[g] + rbk);
        unsigned qb = sb + g * 32768;
        unsigned kb2 = sb + 16384 + g * 32768;
#pragma unroll
        for (int p = 0; p < 4; p++) {
            int f = tid + p * 256;
            int r = f >> 3;
            int cb = (f & 7) * 16;
            unsigned off = sw128(r * 128 + cb);
            CP16(qb + off, qsrc + r * 128 + cb);
            CP16(kb2 + off, ksrc + r * 128 + cb);
        }
        CP_COMMIT();
    }

    float acc[2][8][4];
#pragma unroll
    for (int mi = 0; mi < 2; mi++)
#pragma unroll
        for (int ni = 0; ni < 8; ni++)
#pragma unroll
            for (int u = 0; u < 4; u++) acc[mi][ni][u] = 0.f;

    int wr = wid & 3, wc = wid >> 2, sub = lane >> 3, l7 = lane & 7;
    unsigned Q0 = sb, K0 = sb + 16384, QX = sb + 32768, KX = sb + 49152;

    // stage 0: (0,0)
    CP_WAIT(1); __syncthreads();
#pragma unroll
    for (int ks = 0; ks < 4; ks++) {
        int kb = ks * 32;
        unsigned a0[2][4], bfr[8][2];
        ld_afragB(Q0, wr, sub, l7, kb, a0);
        ld_bfragB(K0, wc, sub, l7, kb, bfr);
        mma_all(acc, a0, bfr);
    }
    // stage 1: (1,0),(0,1),(1,1)
    CP_WAIT(0); __syncthreads();
#pragma unroll
    for (int ks = 0; ks < 4; ks++) {
        int kb = ks * 32;
        unsigned a0[2][4], a1[2][4], bfr[8][2];
        ld_afragB(Q0, wr, sub, l7, kb, a0);
        ld_afragB(QX, wr, sub, l7, kb, a1);
        ld_bfragB(K0, wc, sub, l7, kb, bfr);
        mma_all(acc, a1, bfr);                 // (1,0)
        ld_bfragB(KX, wc, sub, l7, kb, bfr);
        mma_all(acc, a0, bfr);                 // (0,1)
        mma_all(acc, a1, bfr);                 // (1,1)
    }
    // reload qx/kx with split 2 (all reads done)
    __syncthreads();
    {
        const char* qsrc = (const char*)(g_qs[2] + rbq);
        const char* ksrc = (const char*)(g_ks[2] + rbk);
#pragma unroll
        for (int p = 0; p < 4; p++) {
            int f = tid + p * 256;
            int r = f >> 3;
            int cb = (f & 7) * 16;
            unsigned off = sw128(r * 128 + cb);
            CP16(QX + off, qsrc + r * 128 + cb);
            CP16(KX + off, ksrc + r * 128 + cb);
        }
        CP_COMMIT();
    }
    CP_WAIT(0); __syncthreads();
    // stage 2: (2,0),(0,2)
#pragma unroll
    for (int ks = 0; ks < 4; ks++) {
        int kb = ks * 32;
        unsigned a0[2][4], a2[2][4], bfr[8][2];
        ld_afragB(Q0, wr, sub, l7, kb, a0);
        ld_afragB(QX, wr, sub, l7, kb, a2);
        ld_bfragB(K0, wc, sub, l7, kb, bfr);
        mma_all(acc, a2, bfr);                 // (2,0)
        ld_bfragB(KX, wc, sub, l7, kb, bfr);
        mma_all(acc, a0, bfr);                 // (0,2)
    }

    // direct epilogue: transform, store float2 pairs, tilemax atomics
    float* erow = g_eld + ((size_t)bh * LSEQ + i0) * LSEQ + j0;
    int rbase = wr * 32 + (lane >> 2);
    int cbase = wc * 64 + (lane & 3) * 2;
    float mx[2][2] = {{-INFINITY, -INFINITY}, {-INFINITY, -INFINITY}};
#pragma unroll
    for (int mi = 0; mi < 2; mi++) {
#pragma unroll
        for (int hh = 0; hh < 2; hh++) {
            int rloc = rbase + mi * 16 + hh * 8;
            int i = i0 + rloc;
#pragma unroll
            for (int ni = 0; ni < 8; ni++) {
                int cloc = cbase + ni * 8;
                int j = j0 + cloc;
                float e0 = g_dtab[j - i + 2047] * (acc[mi][ni][hh * 2] * 0.125f);
                float e1 = g_dtab[j + 1 - i + 2047] * (acc[mi][ni][hh * 2 + 1] * 0.125f);
                *(float2*)(erow + (size_t)rloc * LSEQ + cloc) = make_float2(e0, e1);
                mx[mi][hh] = fmaxf(mx[mi][hh], fmaxf(e0, e1));
            }
        }
    }
#pragma unroll
    for (int mi = 0; mi < 2; mi++)
#pragma unroll
        for (int hh = 0; hh < 2; hh++) {
            float r = mx[mi][hh];
            r = fmaxf(r, __shfl_xor_sync(0xffffffffu, r, 1));
            r = fmaxf(r, __shfl_xor_sync(0xffffffffu, r, 2));
            if ((lane & 3) == 0) {
                int i = i0 + rbase + mi * 16 + hh * 8;
                unsigned u = __float_as_uint(r);
                unsigned key = (u & 0x80000000u) ? ~u : (u | 0x80000000u);
                atomicMax(&g_tilemax_u[(bh * LSEQ + i) * 16 + blockIdx.x], key);
            }
        }
}

// ---------------- warp-per-row softmax + pool + batched PV ------------------
#define RCAP 128
__global__ void __launch_bounds__(256) k_row6(float* __restrict__ pooled_out) {
    extern __shared__ char rsm[];
    int tid = threadIdx.x, wid = tid >> 5, lane = tid & 31;
    float* p_w = (float*)rsm + wid * 2048;
    unsigned* mC = (unsigned*)(rsm + 65536) + wid * 64;
    unsigned short* cpos_w = (unsigned short*)(rsm + 67584) + wid * RCAP;

    int row = blockIdx.x * 8 + wid;
    int bh = row >> 11;
    int i  = row & 2047;
    int b  = bh >> 3, h = bh & 7;

    float tm = -INFINITY;
    if (lane < 16) {
        unsigned kk = g_tilemax_u[row * 16 + lane];
        unsigned ub = (kk & 0x80000000u) ? (kk ^ 0x80000000u) : ~kk;
        tm = __uint_as_float(ub);
    }
    float mx = tm;
#pragma unroll
    for (int o = 16; o > 0; o >>= 1)
        mx = fmaxf(mx, __shfl_xor_sync(0xffffffffu, mx, o));
    unsigned nd = __ballot_sync(0xffffffffu, tm > mx - 88.0f) & 0xffffu;

    mC[lane] = 0u; mC[lane + 32] = 0u;
    unsigned ti = nd;
    while (ti) {
        int t = __ffs(ti) - 1; ti &= ti - 1;
        *(float4*)(p_w + t * 128 + lane * 4) = make_float4(0.f, 0.f, 0.f, 0.f);
    }
    __syncwarp();

    const float* eldrow = g_eld + (size_t)row * LSEQ;
    float lsum = 0.f;
    ti = nd;
    while (ti) {
        int t = __ffs(ti) - 1; ti &= ti - 1;
        int pos = t * 128 + lane * 4;
        float4 e = *(const float4*)(eldrow + pos);
        float ev[4] = {e.x, e.y, e.z, e.w};
#pragma unroll
        for (int u = 0; u < 4; u++) {
            float arg = ev[u] - mx;
            if (arg > -88.0f) {
                float ex = expf(arg);
                p_w[pos + u] = ex;
                lsum += ex;
                int pp0 = pos + u;
                int lo = (pp0 > 0) ? pp0 - 1 : 0;
                int hi = (pp0 < 2047) ? pp0 + 1 : 2047;
                for (int pp = lo; pp <= hi; pp++)
                    atomicOr(&mC[pp >> 5], 1u << (pp & 31));
            }
        }
    }
    __syncwarp();
#pragma unroll
    for (int o = 16; o > 0; o >>= 1)
        lsum += __shfl_xor_sync(0xffffffffu, lsum, o);
    float S = lsum;

    ti = nd;
    while (ti) {
        int t = __ffs(ti) - 1; ti &= ti - 1;
        int pos = t * 128 + lane * 4;
        float4 pv = *(const float4*)(p_w + pos);
        pv.x /= S; pv.y /= S; pv.z /= S; pv.w /= S;
        *(float4*)(p_w + pos) = pv;
    }
    __syncwarp();

#define PVAL(pos) (((nd >> ((pos) >> 7)) & 1u) ? p_w[(pos)] : 0.f)

    unsigned w0 = mC[lane * 2], w1 = mC[lane * 2 + 1];
    int cnt = __popc(w0) + __popc(w1);
    int incl = cnt;
#pragma unroll
    for (int o = 1; o < 32; o <<= 1) {
        int t = __shfl_up_sync(0xffffffffu, incl, o);
        if (lane >= o) incl += t;
    }
    int basei = incl - cnt;
    int total = __shfl_sync(0xffffffffu, incl, 31);
    {
        int idx = basei;
#pragma unroll
        for (int half = 0; half < 2; half++) {
            unsigned bw = half ? w1 : w0;
            int pbase = lane * 64 + half * 32;
            while (bw) {
                int bp = __ffs((int)bw) - 1;
                bw &= (bw - 1);
                if (idx < RCAP) cpos_w[idx] = (unsigned short)(pbase + bp);
                idx++;
            }
        }
    }
    __syncwarp();
    int cn = (total < RCAP) ? total : RCAP;

    float* prow = pooled_out + (size_t)row * LSEQ;
#pragma unroll 1
    for (int o = 0; o < 16; o++) {
        int pos = o * 128 + lane * 4;
        unsigned bits = (mC[pos >> 5] >> (pos & 31)) & 0xFu;
        float out4[4] = {0.f, 0.f, 0.f, 0.f};
        if (bits) {
#pragma unroll
            for (int u = 0; u < 4; u++) {
                if (bits & (1u << u)) {
                    int p = pos + u;
                    float pm = (p > 0)    ? PVAL(p - 1) : 0.f;
                    float pz = PVAL(p);
                    float pq = (p < 2047) ? PVAL(p + 1) : 0.f;
                    out4[u] = ((pm + pz) + pq) / 3.0f;
                }
            }
        }
        *(float4*)(prow + pos) = make_float4(out4[0], out4[1], out4[2], out4[3]);
    }

    {
        const float* vb = g_vh + (size_t)bh * LSEQ * 64;
        float a0 = 0.f, a1 = 0.f;
#pragma unroll 1
        for (int c0 = 0; c0 < cn; c0 += 8) {
            int nb = cn - c0; if (nb > 8) nb = 8;
            float vl[8], va[8], vq[8];
#pragma unroll
            for (int bq = 0; bq < 8; bq++) {
                if (bq < nb) {
                    int p = cpos_w[c0 + bq];
                    float pm = (p > 0)    ? PVAL(p - 1) : 0.f;
                    float pz = PVAL(p);
                    float pq = (p < 2047) ? PVAL(p + 1) : 0.f;
                    vl[bq] = ((pm + pz) + pq) / 3.0f;
                    const float* vr = vb + (size_t)p * 64;
                    va[bq] = vr[lane];
                    vq[bq] = vr[lane + 32];
                } else { vl[bq] = 0.f; va[bq] = 0.f; vq[bq] = 0.f; }
            }
#pragma unroll
            for (int bq = 0; bq < 8; bq++) {
                a0 = fmaf(vl[bq], va[bq], a0);
                a1 = fmaf(vl[bq], vq[bq], a1);
            }
        }
        float* ob = g_attnout + ((size_t)(b * LSEQ + i)) * DMOD + h * 64;
        ob[lane] = a0;
        ob[lane + 32] = a1;
    }
#undef PVAL
}

// ---------------- residual + LayerNorm (combines fc halves) -----------------
__global__ void k_ln(const float* __restrict__ resid, const float* __restrict__ gamma,
                     const float* __restrict__ beta, float* __restrict__ outp) {
    __shared__ float red[128];
    int m = blockIdx.x;
    int tid = threadIdx.x;
    float4 f0 = *(const float4*)(g_fcout + (size_t)m * 512 + tid * 4);
    float4 f1 = *(const float4*)(g_fcout2 + (size_t)m * 512 + tid * 4);
    float4 r = *(const float4*)(resid + (size_t)m * 512 + tid * 4);
    float y[4] = {(f0.x + f1.x) + r.x, (f0.y + f1.y) + r.y,
                  (f0.z + f1.z) + r.z, (f0.w + f1.w) + r.w};

    float s = (y[0] + y[1]) + (y[2] + y[3]);
    red[tid] = s;
    __syncthreads();
    for (int st = 64; st > 0; st >>= 1) {
        if (tid < st) red[tid] += red[tid + st];
        __syncthreads();
    }
    float mu = red[0] * (1.0f / 512.0f);
    __syncthreads();

    float d[4] = {y[0] - mu, y[1] - mu, y[2] - mu, y[3] - mu};
    float sq = (d[0] * d[0] + d[1] * d[1]) + (d[2] * d[2] + d[3] * d[3]);
    red[tid] = sq;
    __syncthreads();
    for (int st = 64; st > 0; st >>= 1) {
        if (tid < st) red[tid] += red[tid + st];
        __syncthreads();
    }
    float var = red[0] * (1.0f / 512.0f);
    float inv = 1.0f / sqrtf(var + 1e-6f);

    float4 g = *(const float4*)(gamma + tid * 4);
    float4 bb = *(const float4*)(beta + tid * 4);
    float4 o = make_float4(d[0] * inv * g.x + bb.x, d[1] * inv * g.y + bb.y,
                           d[2] * inv * g.z + bb.z, d[3] * inv * g.w + bb.w);
    *(float4*)(outp + (size_t)m * 512 + tid * 4) = o;
}

// ---------------- launch -----------------------------------------------------
#define SMEM3 (98304 + 1024)
#define SMEM2 (67584 + 1024)
#define SMEM_ELD (65536 + 1024)
#define SMEMR (65536 + 2048 + 2048)

extern "C" void kernel_launch(void* const* d_in, const int* in_sizes, int n_in,
                              void* d_out, int out_size) {
    const float* q     = (const float*)d_in[0];
    const float* k     = (const float*)d_in[1];
    const float* v     = (const float*)d_in[2];
    const float* wq    = (const float*)d_in[3];
    const float* wk    = (const float*)d_in[4];
    const float* wv    = (const float*)d_in[5];
    const float* wfc   = (const float*)d_in[6];
    const float* gamma = (const float*)d_in[7];
    const float* beta  = (const float*)d_in[8];

    float* outp = (float*)d_out;            // [B,L,1,D]
    float* pooledp = outp + 2097152;        // [B,H,L,L]

    cudaFuncSetAttribute(k_proj_all, cudaFuncAttributeMaxDynamicSharedMemorySize, SMEM3);
    cudaFuncSetAttribute(k_fc2,      cudaFuncAttributeMaxDynamicSharedMemorySize, SMEM2);
    cudaFuncSetAttribute(k_eld_mma,  cudaFuncAttributeMaxDynamicSharedMemorySize, SMEM_ELD);
    cudaFuncSetAttribute(k_row6,     cudaFuncAttributeMaxDynamicSharedMemorySize, SMEMR);

    k_init<<<2048, 256>>>();
    k_proj_all<<<dim3(4, 32, 3), 256, SMEM3>>>(q, k, v, wq, wk, wv);
    k_eld_mma<<<dim3(16, 16, 16), 256, SMEM_ELD>>>();
    k_row6<<<4096, 256, SMEMR>>>(pooledp);
    k_fc2<<<dim3(4, 32, 2), 256, SMEM2>>>(wfc);
    k_ln<<<4096, 128>>>(q, gamma, beta, outp);
}

// round 16
// speedup vs baseline: 1.0399x; 1.0026x over previous
#include <cuda_runtime.h>
#include <cuda_bf16.h>
#include <math.h>

// B=2, L=2048, H=8, DK=DV=64, D=512, KSZ=3, pad=1
#define NROWS 32768            // B*H*L
#define BH    16               // B*H
#define LSEQ  2048
#define DHEAD 64
#define DMOD  512
#define M4    4096             // B*L

// ---------------- device scratch -------------------------------------------
__device__ float g_vh[BH * LSEQ * DHEAD];
__device__ __align__(128) __nv_bfloat16 g_qs[3][BH * LSEQ * DHEAD];
__device__ __align__(128) __nv_bfloat16 g_ks[3][BH * LSEQ * DHEAD];
__device__ float g_eld[(size_t)BH * LSEQ * LSEQ];   // 268MB logits
__device__ float g_attnout[M4 * DMOD];
__device__ float g_fcout[M4 * DMOD];
__device__ float g_fcout2[M4 * DMOD];
__device__ float g_dtab[4095];
__device__ unsigned int g_tilemax_u[NROWS * 16];    // per-(row, 128col-tile) max
// pre-split GEMM operands (bf16): A slots q:0-2 k:3-5 v:6-7, W same mapping
__device__ __align__(128) __nv_bfloat16 g_psA[8][(size_t)M4 * DMOD];
__device__ __align__(128) __nv_bfloat16 g_psW[8][DMOD * DMOD];

// ---------------- helpers ----------------------------------------------------
__device__ __forceinline__ unsigned smem_u32(const void* p) {
    unsigned a;
    asm("{ .reg .u64 t; cvta.to.shared.u64 t, %1; cvt.u32.u64 %0, t; }" : "=r"(a) : "l"(p));
    return a;
}
__device__ __forceinline__ unsigned sw128(unsigned x) { return x ^ ((x >> 3) & 0x70); }

#define LDSM_X4(r0, r1, r2, r3, addr) \
    asm volatile("ldmatrix.sync.aligned.m8n8.x4.shared.b16 {%0,%1,%2,%3}, [%4];" \
                 : "=r"(r0), "=r"(r1), "=r"(r2), "=r"(r3) : "r"(addr))

#define MMA16816(d, a, b) \
    asm volatile("mma.sync.aligned.m16n8k16.row.col.f32.bf16.bf16.f32 " \
                 "{%0,%1,%2,%3}, {%4,%5,%6,%7}, {%8,%9}, {%0,%1,%2,%3};" \
                 : "+f"((d)[0]), "+f"((d)[1]), "+f"((d)[2]), "+f"((d)[3]) \
                 : "r"((a)[0]), "r"((a)[1]), "r"((a)[2]), "r"((a)[3]), \
                   "r"((b)[0]), "r"((b)[1]))

#define CP16(dst, src) \
    asm volatile("cp.async.cg.shared.global [%0], [%1], 16;" :: "r"(dst), "l"(src))
#define CP_COMMIT() asm volatile("cp.async.commit_group;" ::: "memory")
#define CP_WAIT(n)  asm volatile("cp.async.wait_group %0;" :: "n"(n) : "memory")

extern __shared__ char dsmem[];

// ---------------- shared HMMA inner machinery --------------------------------
template <int NS>
__device__ __forceinline__ void mma_chunk(unsigned sbA, unsigned sbB,
                                          int wr, int wc, int sub, int l7,
                                          float acc[2][8][4]) {
#pragma unroll
    for (int ks = 0; ks < 4; ks++) {
        int kb = ks * 32;
        unsigned afr[NS][2][4];
#pragma unroll
        for (int s = 0; s < NS; s++)
#pragma unroll
            for (int mi = 0; mi < 2; mi++) {
                int r = wr * 32 + mi * 16 + l7 + (sub & 1) * 8;
                int byt = kb + (sub >> 1) * 16;
                unsigned ad = sbA + s * 16384 + sw128((unsigned)(r * 128 + byt));
                LDSM_X4(afr[s][mi][0], afr[s][mi][1], afr[s][mi][2], afr[s][mi][3], ad);
            }
#pragma unroll
        for (int s = 0; s < NS; s++) {
            unsigned bfr[8][2];
#pragma unroll
            for (int np = 0; np < 4; np++) {
                int n = wc * 64 + np * 16 + l7 + (sub >> 1) * 8;
                int byt = kb + (sub & 1) * 16;
                unsigned bd = sbB + s * 16384 + sw128((unsigned)(n * 128 + byt));
                unsigned r0, r1, r2, r3;
                LDSM_X4(r0, r1, r2, r3, bd);
                bfr[np * 2][0] = r0; bfr[np * 2][1] = r1;
                bfr[np * 2 + 1][0] = r2; bfr[np * 2 + 1][1] = r3;
            }
#pragma unroll
            for (int a = 0; a < NS - s; a++)
#pragma unroll
                for (int mi = 0; mi < 2; mi++)
#pragma unroll
                    for (int ni = 0; ni < 8; ni++)
                        MMA16816(acc[mi][ni], afr[a][mi], bfr[ni]);
        }
    }
}

// load pre-split bf16 tile (128 rows x 64 cols, NS splits) into SW128 smem
template <int NS>
__device__ __forceinline__ void load_pre_tile(const __nv_bfloat16* base,
                                              size_t slotStride, int row0,
                                              int kc, char* dst) {
    int tid = threadIdx.x;
#pragma unroll
    for (int s = 0; s < NS; s++) {
        const char* src = (const char*)(base + (size_t)s * slotStride);
#pragma unroll
        for (int p = 0; p < 4; p++) {
            int f = tid + p * 256;
            int r = f >> 3;
            int cb = (f & 7) * 16;
            unsigned off = sw128((unsigned)(r * 128 + cb));
            *(uint4*)(dst + s * 16384 + off) =
                *(const uint4*)(src + ((size_t)(row0 + r) * 512 + kc) * 2 + cb);
        }
    }
}

template <int NS>
__device__ __forceinline__ void gemm_pre(const __nv_bfloat16* Abase,
                                         const __nv_bfloat16* Wbase,
                                         unsigned sb, char* smp,
                                         float acc[2][8][4],
                                         int kbeg, int kend) {
    int tid = threadIdx.x;
    int wid = tid >> 5, lane = tid & 31;
#pragma unroll 1
    for (int kc = kbeg; kc < kend; kc += 64) {
        __syncthreads();
        load_pre_tile<NS>(Abase, (size_t)M4 * DMOD, blockIdx.y * 128, kc, smp);
        load_pre_tile<NS>(Wbase, (size_t)DMOD * DMOD, blockIdx.x * 128, kc,
                          smp + NS * 16384);
        __syncthreads();
        mma_chunk<NS>(sb, sb + NS * 16384, wid & 3, wid >> 2, lane >> 3, lane & 7, acc);
    }
}

// legacy on-the-fly split loader (still used by fc)
template <int NS>
__device__ __forceinline__ void load_split_tile(const float* __restrict__ src,
                                                int row0, int kc, char* dst) {
    int tid = threadIdx.x;
#pragma unroll
    for (int p = 0; p < 8; p++) {
        int f = tid + p * 256;
        int r = f >> 4;
        int c4 = (f & 15) << 2;
        float4 v = *(const float4*)(src + (size_t)(row0 + r) * 512 + kc + c4);
        float xs[4] = {v.x, v.y, v.z, v.w};
        union { __nv_bfloat16 h[4]; uint2 u; } pk[NS];
#pragma unroll
        for (int u = 0; u < 4; u++) {
            float x = xs[u];
#pragma unroll
            for (int s = 0; s < NS; s++) {
                __nv_bfloat16 b = __float2bfloat16(x);
                pk[s].h[u] = b;
                x -= __bfloat162float(b);
            }
        }
        unsigned off = sw128((unsigned)(r * 128 + c4 * 2));
#pragma unroll
        for (int s = 0; s < NS; s++)
            *(uint2*)(dst + s * 16384 + off) = pk[s].u;
    }
}

template <int NS>
__device__ __forceinline__ void gemm_core(const float* A, const float* W,
                                          unsigned sb, char* smp,
                                          float acc[2][8][4],
                                          int kbeg, int kend) {
    int tid = threadIdx.x;
    int wid = tid >> 5, lane = tid & 31;
#pragma unroll 1
    for (int kc = kbeg; kc < kend; kc += 64) {
        __syncthreads();
        load_split_tile<NS>(A, blockIdx.y * 128, kc, smp);
        load_split_tile<NS>(W, blockIdx.x * 128, kc, smp + NS * 16384);
        __syncthreads();
        mma_chunk<NS>(sb, sb + NS * 16384, wid & 3, wid >> 2, lane >> 3, lane & 7, acc);
    }
}

__device__ __forceinline__ void stage_acc(float* stage, float acc[2][8][4],
                                          int wid, int lane) {
    int rbase = (wid & 3) * 32 + (lane >> 2);
    int cbase = (wid >> 2) * 64 + (lane & 3) * 2;
#pragma unroll
    for (int mi = 0; mi < 2; mi++)
#pragma unroll
        for (int ni = 0; ni < 8; ni++)
#pragma unroll
            for (int u = 0; u < 4; u++)
                stage[(rbase + mi * 16 + (u >> 1) * 8) * 132 +
                      cbase + ni * 8 + (u & 1)] = acc[mi][ni][u];
}

// fragment loaders with explicit buffer base
__device__ __forceinline__ void ld_afragB(unsigned abuf, int wr, int sub,
                                          int l7, int kb, unsigned out[2][4]) {
#pragma unroll
    for (int mi = 0; mi < 2; mi++) {
        int r = wr * 32 + mi * 16 + l7 + (sub & 1) * 8;
        int byt = kb + (sub >> 1) * 16;
        unsigned ad = abuf + sw128((unsigned)(r * 128 + byt));
        LDSM_X4(out[mi][0], out[mi][1], out[mi][2], out[mi][3], ad);
    }
}
__device__ __forceinline__ void ld_bfragB(unsigned bbuf, int wc, int sub,
                                          int l7, int kb, unsigned bfr[8][2]) {
#pragma unroll
    for (int np = 0; np < 4; np++) {
        int n = wc * 64 + np * 16 + l7 + (sub >> 1) * 8;
        int byt = kb + (sub & 1) * 16;
        unsigned bd = bbuf + sw128((unsigned)(n * 128 + byt));
        unsigned r0, r1, r2, r3;
        LDSM_X4(r0, r1, r2, r3, bd);
        bfr[np * 2][0] = r0; bfr[np * 2][1] = r1;
        bfr[np * 2 + 1][0] = r2; bfr[np * 2 + 1][1] = r3;
    }
}
__device__ __forceinline__ void mma_all(float acc[2][8][4], unsigned a[2][4],
                                        unsigned b[8][2]) {
#pragma unroll
    for (int mi = 0; mi < 2; mi++)
#pragma unroll
        for (int ni = 0; ni < 8; ni++)
            MMA16816(acc[mi][ni], a[mi], b[ni]);
}

// ---------------- init ------------------------------------------------------
__global__ void k_init() {
    int t = blockIdx.x * blockDim.x + threadIdx.x;
    if (t < 4095) {
        double alpha = -log(0.001 / 7.0 * 3.0);   // ALPHA_C
        g_dtab[t] = (float)(-alpha * (double)(t - 2047));
    }
    if (t < NROWS * 16) g_tilemax_u[t] = 0u;
}

// ---------------- pre-split GEMM operands to bf16 ----------------------------
// z: 0=q 1=k 2=v inputs, 3=wq 4=wk 5=wv weights
__global__ void k_presplit(const float* __restrict__ qi, const float* __restrict__ ki,
                           const float* __restrict__ vi, const float* __restrict__ wq,
                           const float* __restrict__ wk, const float* __restrict__ wv) {
    int z = blockIdx.z;
    int si = (z >= 3) ? z - 3 : z;
    bool isW = z >= 3;
    const float* S = isW ? (si == 0 ? wq : si == 1 ? wk : wv)
                         : (si == 0 ? qi : si == 1 ? ki : vi);
    int NS = (si == 2) ? 2 : 3;
    size_t count = isW ? (size_t)DMOD * DMOD : (size_t)M4 * DMOD;
    size_t idx4 = ((size_t)blockIdx.x * 256 + threadIdx.x) * 4;
    if (idx4 >= count) return;

    float4 v = *(const float4*)(S + idx4);
    float xs[4] = {v.x, v.y, v.z, v.w};
    union { __nv_bfloat16 h[4]; uint2 u; } pk[3];
#pragma unroll
    for (int u = 0; u < 4; u++) {
        float x = xs[u];
#pragma unroll
        for (int s = 0; s < 3; s++) {
            __nv_bfloat16 b = __float2bfloat16(x);
            pk[s].h[u] = b;
            x -= __bfloat162float(b);
        }
    }
    int slot0 = si * 3;
    if (isW) {
#pragma unroll
        for (int s = 0; s < 3; s++)
            if (s < NS) *(uint2*)(g_psW[slot0 + s] + idx4) = pk[s].u;
    } else {
#pragma unroll
        for (int s = 0; s < 3; s++)
            if (s < NS) *(uint2*)(g_psA[slot0 + s] + idx4) = pk[s].u;
    }
}

// ---------------- fused q/k/v projection (pre-split operands) ----------------
__global__ void __launch_bounds__(256, 2) k_proj_all() {
    int z = blockIdx.z;
    int tid = threadIdx.x;
    int wid = tid >> 5, lane = tid & 31;

    unsigned raw = smem_u32(dsmem);
    unsigned sb = (raw + 1023) & ~1023u;
    char* smp = dsmem + (sb - raw);

    float acc[2][8][4];
#pragma unroll
    for (int mi = 0; mi < 2; mi++)
#pragma unroll
        for (int ni = 0; ni < 8; ni++)
#pragma unroll
            for (int u = 0; u < 4; u++) acc[mi][ni][u] = 0.f;

    const __nv_bfloat16* Ab = g_psA[z * 3];
    const __nv_bfloat16* Wb = g_psW[z * 3];
    if (z == 2) {
        gemm_pre<2>(Ab, Wb, sb, smp, acc, 0, 512);
    } else {
        gemm_pre<3>(Ab, Wb, sb, smp, acc, 0, 512);
    }

    __syncthreads();
    float* stage = (float*)smp;
    stage_acc(stage, acc, wid, lane);
    __syncthreads();

    int m0 = blockIdx.y * 128, n0 = blockIdx.x * 128;
    if (z == 2) {
#pragma unroll
        for (int p = 0; p < 16; p++) {
            int f = tid + p * 256;
            int r = f >> 5, q = f & 31;
            int m = m0 + r, bb = m >> 11, l = m & 2047;
            int n = n0 + q * 4, h = n >> 6, dk = n & 63;
            float4 v = *(const float4*)(stage + r * 132 + q * 4);
            *(float4*)(g_vh + ((size_t)(bb * 8 + h) * LSEQ + l) * 64 + dk) = v;
        }
    } else {
        __nv_bfloat16* S0 = z ? g_ks[0] : g_qs[0];
        __nv_bfloat16* S1 = z ? g_ks[1] : g_qs[1];
        __nv_bfloat16* S2 = z ? g_ks[2] : g_qs[2];
#pragma unroll
        for (int p = 0; p < 16; p++) {
            int f = tid + p * 256;
            int r = f >> 5, q = f & 31;
            int m = m0 + r, bb = m >> 11, l = m & 2047;
            int n = n0 + q * 4, h = n >> 6, dk = n & 63;
            float4 v = *(const float4*)(stage + r * 132 + q * 4);
            float xs[4] = {v.x, v.y, v.z, v.w};
            union { __nv_bfloat16 h4[4]; uint2 u; } p0, p1, p2;
#pragma unroll
            for (int u = 0; u < 4; u++) {
                float x = xs[u];
                __nv_bfloat16 b0 = __float2bfloat16(x);
                float r1 = x - __bfloat162float(b0);
                __nv_bfloat16 b1 = __float2bfloat16(r1);
                float r2 = r1 - __bfloat162float(b1);
                __nv_bfloat16 b2 = __float2bfloat16(r2);
                p0.h4[u] = b0; p1.h4[u] = b1; p2.h4[u] = b2;
            }
            size_t off = ((size_t)(bb * 8 + h) * LSEQ + l) * 64 + dk;
            *(uint2*)(S0 + off) = p0.u;
            *(uint2*)(S1 + off) = p1.u;
            *(uint2*)(S2 + off) = p2.u;
        }
    }
}

// ---------------- fc projection: split-K halves ------------------------------
__global__ void __launch_bounds__(256, 2) k_fc2(const float* __restrict__ wfc) {
    int tid = threadIdx.x;
    int wid = tid >> 5, lane = tid & 31;
    unsigned raw = smem_u32(dsmem);
    unsigned sb = (raw + 1023) & ~1023u;
    char* smp = dsmem + (sb - raw);

    float acc[2][8][4];
#pragma unroll
    for (int mi = 0; mi < 2; mi++)
#pragma unroll
        for (int ni = 0; ni < 8; ni++)
#pragma unroll
            for (int u = 0; u < 4; u++) acc[mi][ni][u] = 0.f;

    int kh = blockIdx.z;   // 0 or 1
    gemm_core<2>(g_attnout, wfc, sb, smp, acc, kh * 256, kh * 256 + 256);

    __syncthreads();
    float* stage = (float*)smp;
    stage_acc(stage, acc, wid, lane);
    __syncthreads();

    float* dst = kh ? g_fcout2 : g_fcout;
    int m0 = blockIdx.y * 128, n0 = blockIdx.x * 128;
#pragma unroll
    for (int p = 0; p < 16; p++) {
        int f = tid + p * 256;
        int r = f >> 5, q = f & 31;
        float4 v = *(const float4*)(stage + r * 132 + q * 4);
        *(float4*)(dst + (size_t)(m0 + r) * 512 + n0 + q * 4) = v;
    }
}

// ---------------- eld logits: pipelined HMMA bf16x3, direct store -----------
__global__ void __launch_bounds__(256, 2) k_eld_mma() {
    int tid = threadIdx.x;
    int wid = tid >> 5, lane = tid & 31;
    int bh = blockIdx.z;
    int i0 = blockIdx.y * 128, j0 = blockIdx.x * 128;

    unsigned raw = smem_u32(dsmem);
    unsigned sb = (raw + 1023) & ~1023u;

    size_t rbq = ((size_t)bh * LSEQ + i0) * 64;
    size_t rbk = ((size_t)bh * LSEQ + j0) * 64;

#pragma unroll
    for (int g = 0; g < 2; g++) {
        const char* qsrc = (const char*)(g_qs[g] + rbq);
        const char* ksrc = (const char*)(g_ks[g] + rbk);
        unsigned qb = sb + g * 32768;
        unsigned kb2 = sb + 16384 + g * 32768;
#pragma unroll
        for (int p = 0; p < 4; p++) {
            int f = tid + p * 256;
            int r = f >> 3;
            int cb = (f & 7) * 16;
            unsigned off = sw128(r * 128 + cb);
            CP16(qb + off, qsrc + r * 128 + cb);
            CP16(kb2 + off, ksrc + r * 128 + cb);
        }
        CP_COMMIT();
    }

    float acc[2][8][4];
#pragma unroll
    for (int mi = 0; mi < 2; mi++)
#pragma unroll
        for (int ni = 0; ni < 8; ni++)
#pragma unroll
            for (int u = 0; u < 4; u++) acc[mi][ni][u] = 0.f;

    int wr = wid & 3, wc = wid >> 2, sub = lane >> 3, l7 = lane & 7;
    unsigned Q0 = sb, K0 = sb + 16384, QX = sb + 32768, KX = sb + 49152;

    CP_WAIT(1); __syncthreads();
#pragma unroll
    for (int ks = 0; ks < 4; ks++) {
        int kb = ks * 32;
        unsigned a0[2][4], bfr[8][2];
        ld_afragB(Q0, wr, sub, l7, kb, a0);
        ld_bfragB(K0, wc, sub, l7, kb, bfr);
        mma_all(acc, a0, bfr);
    }
    CP_WAIT(0); __syncthreads();
#pragma unroll
    for (int ks = 0; ks < 4; ks++) {
        int kb = ks * 32;
        unsigned a0[2][4], a1[2][4], bfr[8][2];
        ld_afragB(Q0, wr, sub, l7, kb, a0);
        ld_afragB(QX, wr, sub, l7, kb, a1);
        ld_bfragB(K0, wc, sub, l7, kb, bfr);
        mma_all(acc, a1, bfr);                 // (1,0)
        ld_bfragB(KX, wc, sub, l7, kb, bfr);
        mma_all(acc, a0, bfr);                 // (0,1)
        mma_all(acc, a1, bfr);                 // (1,1)
    }
    __syncthreads();
    {
        const char* qsrc = (const char*)(g_qs[2] + rbq);
        const char* ksrc = (const char*)(g_ks[2] + rbk);
#pragma unroll
        for (int p = 0; p < 4; p++) {
            int f = tid + p * 256;
            int r = f >> 3;
            int cb = (f & 7) * 16;
            unsigned off = sw128(r * 128 + cb);
            CP16(QX + off, qsrc + r * 128 + cb);
            CP16(KX + off, ksrc + r * 128 + cb);
        }
        CP_COMMIT();
    }
    CP_WAIT(0); __syncthreads();
#pragma unroll
    for (int ks = 0; ks < 4; ks++) {
        int kb = ks * 32;
        unsigned a0[2][4], a2[2][4], bfr[8][2];
        ld_afragB(Q0, wr, sub, l7, kb, a0);
        ld_afragB(QX, wr, sub, l7, kb, a2);
        ld_bfragB(K0, wc, sub, l7, kb, bfr);
        mma_all(acc, a2, bfr);                 // (2,0)
        ld_bfragB(KX, wc, sub, l7, kb, bfr);
        mma_all(acc, a0, bfr);                 // (0,2)
    }

    float* erow = g_eld + ((size_t)bh * LSEQ + i0) * LSEQ + j0;
    int rbase = wr * 32 + (lane >> 2);
    int cbase = wc * 64 + (lane & 3) * 2;
    float mx[2][2] = {{-INFINITY, -INFINITY}, {-INFINITY, -INFINITY}};
#pragma unroll
    for (int mi = 0; mi < 2; mi++) {
#pragma unroll
        for (int hh = 0; hh < 2; hh++) {
            int rloc = rbase + mi * 16 + hh * 8;
            int i = i0 + rloc;
#pragma unroll
            for (int ni = 0; ni < 8; ni++) {
                int cloc = cbase + ni * 8;
                int j = j0 + cloc;
                float e0 = g_dtab[j - i + 2047] * (acc[mi][ni][hh * 2] * 0.125f);
                float e1 = g_dtab[j + 1 - i + 2047] * (acc[mi][ni][hh * 2 + 1] * 0.125f);
                *(float2*)(erow + (size_t)rloc * LSEQ + cloc) = make_float2(e0, e1);
                mx[mi][hh] = fmaxf(mx[mi][hh], fmaxf(e0, e1));
            }
        }
    }
#pragma unroll
    for (int mi = 0; mi < 2; mi++)
#pragma unroll
        for (int hh = 0; hh < 2; hh++) {
            float r = mx[mi][hh];
            r = fmaxf(r, __shfl_xor_sync(0xffffffffu, r, 1));
            r = fmaxf(r, __shfl_xor_sync(0xffffffffu, r, 2));
            if ((lane & 3) == 0) {
                int i = i0 + rbase + mi * 16 + hh * 8;
                unsigned u = __float_as_uint(r);
                unsigned key = (u & 0x80000000u) ? ~u : (u | 0x80000000u);
                atomicMax(&g_tilemax_u[(bh * LSEQ + i) * 16 + blockIdx.x], key);
            }
        }
}

// ---------------- warp-per-row softmax + pool + batched PV ------------------
#define RCAP 128
__global__ void __launch_bounds__(256) k_row6(float* __restrict__ pooled_out) {
    extern __shared__ char rsm[];
    int tid = threadIdx.x, wid = tid >> 5, lane = tid & 31;
    float* p_w = (float*)rsm + wid * 2048;
    unsigned* mC = (unsigned*)(rsm + 65536) + wid * 64;
    unsigned short* cpos_w = (unsigned short*)(rsm + 67584) + wid * RCAP;

    int row = blockIdx.x * 8 + wid;
    int bh = row >> 11;
    int i  = row & 2047;
    int b  = bh >> 3, h = bh & 7;

    float tm = -INFINITY;
    if (lane < 16) {
        unsigned kk = g_tilemax_u[row * 16 + lane];
        unsigned ub = (kk & 0x80000000u) ? (kk ^ 0x80000000u) : ~kk;
        tm = __uint_as_float(ub);
    }
    float mx = tm;
#pragma unroll
    for (int o = 16; o > 0; o >>= 1)
        mx = fmaxf(mx, __shfl_xor_sync(0xffffffffu, mx, o));
    unsigned nd = __ballot_sync(0xffffffffu, tm > mx - 88.0f) & 0xffffu;

    mC[lane] = 0u; mC[lane + 32] = 0u;
    unsigned ti = nd;
    while (ti) {
        int t = __ffs(ti) - 1; ti &= ti - 1;
        *(float4*)(p_w + t * 128 + lane * 4) = make_float4(0.f, 0.f, 0.f, 0.f);
    }
    __syncwarp();

    const float* eldrow = g_eld + (size_t)row * LSEQ;
    float lsum = 0.f;
    ti = nd;
    while (ti) {
        int t = __ffs(ti) - 1; ti &= ti - 1;
        int pos = t * 128 + lane * 4;
        float4 e = *(const float4*)(eldrow + pos);
        float ev[4] = {e.x, e.y, e.z, e.w};
#pragma unroll
        for (int u = 0; u < 4; u++) {
            float arg = ev[u] - mx;
            if (arg > -88.0f) {
                float ex = expf(arg);
                p_w[pos + u] = ex;
                lsum += ex;
                int pp0 = pos + u;
                int lo = (pp0 > 0) ? pp0 - 1 : 0;
                int hi = (pp0 < 2047) ? pp0 + 1 : 2047;
                for (int pp = lo; pp <= hi; pp++)
                    atomicOr(&mC[pp >> 5], 1u << (pp & 31));
            }
        }
    }
    __syncwarp();
#pragma unroll
    for (int o = 16; o > 0; o >>= 1)
        lsum += __shfl_xor_sync(0xffffffffu, lsum, o);
    float S = lsum;

    ti = nd;
    while (ti) {
        int t = __ffs(ti) - 1; ti &= ti - 1;
        int pos = t * 128 + lane * 4;
        float4 pv = *(const float4*)(p_w + pos);
        pv.x /= S; pv.y /= S; pv.z /= S; pv.w /= S;
        *(float4*)(p_w + pos) = pv;
    }
    __syncwarp();

#define PVAL(pos) (((nd >> ((pos) >> 7)) & 1u) ? p_w[(pos)] : 0.f)

    unsigned w0 = mC[lane * 2], w1 = mC[lane * 2 + 1];
    int cnt = __popc(w0) + __popc(w1);
    int incl = cnt;
#pragma unroll
    for (int o = 1; o < 32; o <<= 1) {
        int t = __shfl_up_sync(0xffffffffu, incl, o);
        if (lane >= o) incl += t;
    }
    int basei = incl - cnt;
    int total = __shfl_sync(0xffffffffu, incl, 31);
    {
        int idx = basei;
#pragma unroll
        for (int half = 0; half < 2; half++) {
            unsigned bw = half ? w1 : w0;
            int pbase = lane * 64 + half * 32;
            while (bw) {
                int bp = __ffs((int)bw) - 1;
                bw &= (bw - 1);
                if (idx < RCAP) cpos_w[idx] = (unsigned short)(pbase + bp);
                idx++;
            }
        }
    }
    __syncwarp();
    int cn = (total < RCAP) ? total : RCAP;

    float* prow = pooled_out + (size_t)row * LSEQ;
#pragma unroll 1
    for (int o = 0; o < 16; o++) {
        int pos = o * 128 + lane * 4;
        unsigned bits = (mC[pos >> 5] >> (pos & 31)) & 0xFu;
        float out4[4] = {0.f, 0.f, 0.f, 0.f};
        if (bits) {
#pragma unroll
            for (int u = 0; u < 4; u++) {
                if (bits & (1u << u)) {
                    int p = pos + u;
                    float pm = (p > 0)    ? PVAL(p - 1) : 0.f;
                    float pz = PVAL(p);
                    float pq = (p < 2047) ? PVAL(p + 1) : 0.f;
                    out4[u] = ((pm + pz) + pq) / 3.0f;
                }
            }
        }
        *(float4*)(prow + pos) = make_float4(out4[0], out4[1], out4[2], out4[3]);
    }

    {
        const float* vb = g_vh + (size_t)bh * LSEQ * 64;
        float a0 = 0.f, a1 = 0.f;
#pragma unroll 1
        for (int c0 = 0; c0 < cn; c0 += 8) {
            int nb = cn - c0; if (nb > 8) nb = 8;
            float vl[8], va[8], vq[8];
#pragma unroll
            for (int bq = 0; bq < 8; bq++) {
                if (bq < nb) {
                    int p = cpos_w[c0 + bq];
                    float pm = (p > 0)    ? PVAL(p - 1) : 0.f;
                    float pz = PVAL(p);
                    float pq = (p < 2047) ? PVAL(p + 1) : 0.f;
                    vl[bq] = ((pm + pz) + pq) / 3.0f;
                    const float* vr = vb + (size_t)p * 64;
                    va[bq] = vr[lane];
                    vq[bq] = vr[lane + 32];
                } else { vl[bq] = 0.f; va[bq] = 0.f; vq[bq] = 0.f; }
            }
#pragma unroll
            for (int bq = 0; bq < 8; bq++) {
                a0 = fmaf(vl[bq], va[bq], a0);
                a1 = fmaf(vl[bq], vq[bq], a1);
            }
        }
        float* ob = g_attnout + ((size_t)(b * LSEQ + i)) * DMOD + h * 64;
        ob[lane] = a0;
        ob[lane + 32] = a1;
    }
#undef PVAL
}

// ---------------- residual + LayerNorm (combines fc halves) -----------------
__global__ void k_ln(const float* __restrict__ resid, const float* __restrict__ gamma,
                     const float* __restrict__ beta, float* __restrict__ outp) {
    __shared__ float red[128];
    int m = blockIdx.x;
    int tid = threadIdx.x;
    float4 f0 = *(const float4*)(g_fcout + (size_t)m * 512 + tid * 4);
    float4 f1 = *(const float4*)(g_fcout2 + (size_t)m * 512 + tid * 4);
    float4 r = *(const float4*)(resid + (size_t)m * 512 + tid * 4);
    float y[4] = {(f0.x + f1.x) + r.x, (f0.y + f1.y) + r.y,
                  (f0.z + f1.z) + r.z, (f0.w + f1.w) + r.w};

    float s = (y[0] + y[1]) + (y[2] + y[3]);
    red[tid] = s;
    __syncthreads();
    for (int st = 64; st > 0; st >>= 1) {
        if (tid < st) red[tid] += red[tid + st];
        __syncthreads();
    }
    float mu = red[0] * (1.0f / 512.0f);
    __syncthreads();

    float d[4] = {y[0] - mu, y[1] - mu, y[2] - mu, y[3] - mu};
    float sq = (d[0] * d[0] + d[1] * d[1]) + (d[2] * d[2] + d[3] * d[3]);
    red[tid] = sq;
    __syncthreads();
    for (int st = 64; st > 0; st >>= 1) {
        if (tid < st) red[tid] += red[tid + st];
        __syncthreads();
    }
    float var = red[0] * (1.0f / 512.0f);
    float inv = 1.0f / sqrtf(var + 1e-6f);

    float4 g = *(const float4*)(gamma + tid * 4);
    float4 bb = *(const float4*)(beta + tid * 4);
    float4 o = make_float4(d[0] * inv * g.x + bb.x, d[1] * inv * g.y + bb.y,
                           d[2] * inv * g.z + bb.z, d[3] * inv * g.w + bb.w);
    *(float4*)(outp + (size_t)m * 512 + tid * 4) = o;
}

// ---------------- launch -----------------------------------------------------
#define SMEM3 (98304 + 1024)
#define SMEM2 (67584 + 1024)
#define SMEM_ELD (65536 + 1024)
#define SMEMR (65536 + 2048 + 2048)

extern "C" void kernel_launch(void* const* d_in, const int* in_sizes, int n_in,
                              void* d_out, int out_size) {
    const float* q     = (const float*)d_in[0];
    const float* k     = (const float*)d_in[1];
    const float* v     = (const float*)d_in[2];
    const float* wq    = (const float*)d_in[3];
    const float* wk    = (const float*)d_in[4];
    const float* wv    = (const float*)d_in[5];
    const float* wfc   = (const float*)d_in[6];
    const float* gamma = (const float*)d_in[7];
    const float* beta  = (const float*)d_in[8];

    float* outp = (float*)d_out;            // [B,L,1,D]
    float* pooledp = outp + 2097152;        // [B,H,L,L]

    cudaFuncSetAttribute(k_proj_all, cudaFuncAttributeMaxDynamicSharedMemorySize, SMEM3);
    cudaFuncSetAttribute(k_fc2,      cudaFuncAttributeMaxDynamicSharedMemorySize, SMEM2);
    cudaFuncSetAttribute(k_eld_mma,  cudaFuncAttributeMaxDynamicSharedMemorySize, SMEM_ELD);
    cudaFuncSetAttribute(k_row6,     cudaFuncAttributeMaxDynamicSharedMemorySize, SMEMR);

    k_init<<<2048, 256>>>();
    k_presplit<<<dim3(2048, 1, 6), 256>>>(q, k, v, wq, wk, wv);
    k_proj_all<<<dim3(4, 32, 3), 256, SMEM3>>>();
    k_eld_mma<<<dim3(16, 16, 16), 256, SMEM_ELD>>>();
    k_row6<<<4096, 256, SMEMR>>>(pooledp);
    k_fc2<<<dim3(4, 32, 2), 256, SMEM2>>>(wfc);
    k_ln<<<4096, 128>>>(q, gamma, beta, outp);
}

// round 17
// speedup vs baseline: 1.1908x; 1.1451x over previous
#include <cuda_runtime.h>
#include <cuda_bf16.h>
#include <cuda_fp16.h>
#include <math.h>

// B=2, L=2048, H=8, DK=DV=64, D=512, KSZ=3, pad=1
#define NROWS 32768            // B*H*L
#define BH    16               // B*H
#define LSEQ  2048
#define DHEAD 64
#define DMOD  512
#define M4    4096             // B*L

// ---------------- device scratch -------------------------------------------
__device__ float g_vh[BH * LSEQ * DHEAD];
__device__ __align__(128) __half g_qs[2][BH * LSEQ * DHEAD];   // fp16x2 splits
__device__ __align__(128) __half g_ks[2][BH * LSEQ * DHEAD];
__device__ float g_eld[(size_t)BH * LSEQ * LSEQ];   // 268MB logits
__device__ float g_attnout[M4 * DMOD];
__device__ float g_fcout[M4 * DMOD];
__device__ float g_fcout2[M4 * DMOD];
__device__ float g_dtab[4095];
__device__ unsigned int g_tilemax_u[NROWS * 16];    // per-(row, 128col-tile) max
// pre-split GEMM operands (bf16): A slots q:0-2 k:3-5 v:6-7, W same mapping
__device__ __align__(128) __nv_bfloat16 g_psA[8][(size_t)M4 * DMOD];
__device__ __align__(128) __nv_bfloat16 g_psW[8][DMOD * DMOD];

// ---------------- helpers ----------------------------------------------------
__device__ __forceinline__ unsigned smem_u32(const void* p) {
    unsigned a;
    asm("{ .reg .u64 t; cvta.to.shared.u64 t, %1; cvt.u32.u64 %0, t; }" : "=r"(a) : "l"(p));
    return a;
}
__device__ __forceinline__ unsigned sw128(unsigned x) { return x ^ ((x >> 3) & 0x70); }

#define LDSM_X4(r0, r1, r2, r3, addr) \
    asm volatile("ldmatrix.sync.aligned.m8n8.x4.shared.b16 {%0,%1,%2,%3}, [%4];" \
                 : "=r"(r0), "=r"(r1), "=r"(r2), "=r"(r3) : "r"(addr))

#define MMA16816(d, a, b) \
    asm volatile("mma.sync.aligned.m16n8k16.row.col.f32.bf16.bf16.f32 " \
                 "{%0,%1,%2,%3}, {%4,%5,%6,%7}, {%8,%9}, {%0,%1,%2,%3};" \
                 : "+f"((d)[0]), "+f"((d)[1]), "+f"((d)[2]), "+f"((d)[3]) \
                 : "r"((a)[0]), "r"((a)[1]), "r"((a)[2]), "r"((a)[3]), \
                   "r"((b)[0]), "r"((b)[1]))

#define MMA16816H(d, a, b) \
    asm volatile("mma.sync.aligned.m16n8k16.row.col.f32.f16.f16.f32 " \
                 "{%0,%1,%2,%3}, {%4,%5,%6,%7}, {%8,%9}, {%0,%1,%2,%3};" \
                 : "+f"((d)[0]), "+f"((d)[1]), "+f"((d)[2]), "+f"((d)[3]) \
                 : "r"((a)[0]), "r"((a)[1]), "r"((a)[2]), "r"((a)[3]), \
                   "r"((b)[0]), "r"((b)[1]))

#define CP16(dst, src) \
    asm volatile("cp.async.cg.shared.global [%0], [%1], 16;" :: "r"(dst), "l"(src))
#define CP_COMMIT() asm volatile("cp.async.commit_group;" ::: "memory")
#define CP_WAIT(n)  asm volatile("cp.async.wait_group %0;" :: "n"(n) : "memory")

extern __shared__ char dsmem[];

// ---------------- shared HMMA inner machinery (bf16, proj/fc) ----------------
template <int NS>
__device__ __forceinline__ void mma_chunk(unsigned sbA, unsigned sbB,
                                          int wr, int wc, int sub, int l7,
                                          float acc[2][8][4]) {
#pragma unroll
    for (int ks = 0; ks < 4; ks++) {
        int kb = ks * 32;
        unsigned afr[NS][2][4];
#pragma unroll
        for (int s = 0; s < NS; s++)
#pragma unroll
            for (int mi = 0; mi < 2; mi++) {
                int r = wr * 32 + mi * 16 + l7 + (sub & 1) * 8;
                int byt = kb + (sub >> 1) * 16;
                unsigned ad = sbA + s * 16384 + sw128((unsigned)(r * 128 + byt));
                LDSM_X4(afr[s][mi][0], afr[s][mi][1], afr[s][mi][2], afr[s][mi][3], ad);
            }
#pragma unroll
        for (int s = 0; s < NS; s++) {
            unsigned bfr[8][2];
#pragma unroll
            for (int np = 0; np < 4; np++) {
                int n = wc * 64 + np * 16 + l7 + (sub >> 1) * 8;
                int byt = kb + (sub & 1) * 16;
                unsigned bd = sbB + s * 16384 + sw128((unsigned)(n * 128 + byt));
                unsigned r0, r1, r2, r3;
                LDSM_X4(r0, r1, r2, r3, bd);
                bfr[np * 2][0] = r0; bfr[np * 2][1] = r1;
                bfr[np * 2 + 1][0] = r2; bfr[np * 2 + 1][1] = r3;
            }
#pragma unroll
            for (int a = 0; a < NS - s; a++)
#pragma unroll
                for (int mi = 0; mi < 2; mi++)
#pragma unroll
                    for (int ni = 0; ni < 8; ni++)
                        MMA16816(acc[mi][ni], afr[a][mi], bfr[ni]);
        }
    }
}

// load pre-split bf16 tile (128 rows x 64 cols, NS splits) into SW128 smem
template <int NS>
__device__ __forceinline__ void load_pre_tile(const __nv_bfloat16* base,
                                              size_t slotStride, int row0,
                                              int kc, char* dst) {
    int tid = threadIdx.x;
#pragma unroll
    for (int s = 0; s < NS; s++) {
        const char* src = (const char*)(base + (size_t)s * slotStride);
#pragma unroll
        for (int p = 0; p < 4; p++) {
            int f = tid + p * 256;
            int r = f >> 3;
            int cb = (f & 7) * 16;
            unsigned off = sw128((unsigned)(r * 128 + cb));
            *(uint4*)(dst + s * 16384 + off) =
                *(const uint4*)(src + ((size_t)(row0 + r) * 512 + kc) * 2 + cb);
        }
    }
}

template <int NS>
__device__ __forceinline__ void gemm_pre(const __nv_bfloat16* Abase,
                                         const __nv_bfloat16* Wbase,
                                         unsigned sb, char* smp,
                                         float acc[2][8][4],
                                         int kbeg, int kend) {
    int tid = threadIdx.x;
    int wid = tid >> 5, lane = tid & 31;
#pragma unroll 1
    for (int kc = kbeg; kc < kend; kc += 64) {
        __syncthreads();
        load_pre_tile<NS>(Abase, (size_t)M4 * DMOD, blockIdx.y * 128, kc, smp);
        load_pre_tile<NS>(Wbase, (size_t)DMOD * DMOD, blockIdx.x * 128, kc,
                          smp + NS * 16384);
        __syncthreads();
        mma_chunk<NS>(sb, sb + NS * 16384, wid & 3, wid >> 2, lane >> 3, lane & 7, acc);
    }
}

// legacy on-the-fly split loader (fc)
template <int NS>
__device__ __forceinline__ void load_split_tile(const float* __restrict__ src,
                                                int row0, int kc, char* dst) {
    int tid = threadIdx.x;
#pragma unroll
    for (int p = 0; p < 8; p++) {
        int f = tid + p * 256;
        int r = f >> 4;
        int c4 = (f & 15) << 2;
        float4 v = *(const float4*)(src + (size_t)(row0 + r) * 512 + kc + c4);
        float xs[4] = {v.x, v.y, v.z, v.w};
        union { __nv_bfloat16 h[4]; uint2 u; } pk[NS];
#pragma unroll
        for (int u = 0; u < 4; u++) {
            float x = xs[u];
#pragma unroll
            for (int s = 0; s < NS; s++) {
                __nv_bfloat16 b = __float2bfloat16(x);
                pk[s].h[u] = b;
                x -= __bfloat162float(b);
            }
        }
        unsigned off = sw128((unsigned)(r * 128 + c4 * 2));
#pragma unroll
        for (int s = 0; s < NS; s++)
            *(uint2*)(dst + s * 16384 + off) = pk[s].u;
    }
}

template <int NS>
__device__ __forceinline__ void gemm_core(const float* A, const float* W,
                                          unsigned sb, char* smp,
                                          float acc[2][8][4],
                                          int kbeg, int kend) {
    int tid = threadIdx.x;
    int wid = tid >> 5, lane = tid & 31;
#pragma unroll 1
    for (int kc = kbeg; kc < kend; kc += 64) {
        __syncthreads();
        load_split_tile<NS>(A, blockIdx.y * 128, kc, smp);
        load_split_tile<NS>(W, blockIdx.x * 128, kc, smp + NS * 16384);
        __syncthreads();
        mma_chunk<NS>(sb, sb + NS * 16384, wid & 3, wid >> 2, lane >> 3, lane & 7, acc);
    }
}

__device__ __forceinline__ void stage_acc(float* stage, float acc[2][8][4],
                                          int wid, int lane) {
    int rbase = (wid & 3) * 32 + (lane >> 2);
    int cbase = (wid >> 2) * 64 + (lane & 3) * 2;
#pragma unroll
    for (int mi = 0; mi < 2; mi++)
#pragma unroll
        for (int ni = 0; ni < 8; ni++)
#pragma unroll
            for (int u = 0; u < 4; u++)
                stage[(rbase + mi * 16 + (u >> 1) * 8) * 132 +
                      cbase + ni * 8 + (u & 1)] = acc[mi][ni][u];
}

// fragment loaders with explicit buffer base
__device__ __forceinline__ void ld_afragB(unsigned abuf, int wr, int sub,
                                          int l7, int kb, unsigned out[2][4]) {
#pragma unroll
    for (int mi = 0; mi < 2; mi++) {
        int r = wr * 32 + mi * 16 + l7 + (sub & 1) * 8;
        int byt = kb + (sub >> 1) * 16;
        unsigned ad = abuf + sw128((unsigned)(r * 128 + byt));
        LDSM_X4(out[mi][0], out[mi][1], out[mi][2], out[mi][3], ad);
    }
}
__device__ __forceinline__ void ld_bfragB(unsigned bbuf, int wc, int sub,
                                          int l7, int kb, unsigned bfr[8][2]) {
#pragma unroll
    for (int np = 0; np < 4; np++) {
        int n = wc * 64 + np * 16 + l7 + (sub >> 1) * 8;
        int byt = kb + (sub & 1) * 16;
        unsigned bd = bbuf + sw128((unsigned)(n * 128 + byt));
        unsigned r0, r1, r2, r3;
        LDSM_X4(r0, r1, r2, r3, bd);
        bfr[np * 2][0] = r0; bfr[np * 2][1] = r1;
        bfr[np * 2 + 1][0] = r2; bfr[np * 2 + 1][1] = r3;
    }
}
__device__ __forceinline__ void mma_allH(float acc[2][8][4], unsigned a[2][4],
                                         unsigned b[8][2]) {
#pragma unroll
    for (int mi = 0; mi < 2; mi++)
#pragma unroll
        for (int ni = 0; ni < 8; ni++)
            MMA16816H(acc[mi][ni], a[mi], b[ni]);
}

// ---------------- init ------------------------------------------------------
__global__ void k_init() {
    int t = blockIdx.x * blockDim.x + threadIdx.x;
    if (t < 4095) {
        double alpha = -log(0.001 / 7.0 * 3.0);   // ALPHA_C
        g_dtab[t] = (float)(-alpha * (double)(t - 2047));
    }
    if (t < NROWS * 16) g_tilemax_u[t] = 0u;
}

// ---------------- pre-split GEMM operands to bf16 ----------------------------
__global__ void k_presplit(const float* __restrict__ qi, const float* __restrict__ ki,
                           const float* __restrict__ vi, const float* __restrict__ wq,
                           const float* __restrict__ wk, const float* __restrict__ wv) {
    int z = blockIdx.z;
    int si = (z >= 3) ? z - 3 : z;
    bool isW = z >= 3;
    const float* S = isW ? (si == 0 ? wq : si == 1 ? wk : wv)
                         : (si == 0 ? qi : si == 1 ? ki : vi);
    int NS = (si == 2) ? 2 : 3;
    size_t count = isW ? (size_t)DMOD * DMOD : (size_t)M4 * DMOD;
    size_t idx4 = ((size_t)blockIdx.x * 256 + threadIdx.x) * 4;
    if (idx4 >= count) return;

    float4 v = *(const float4*)(S + idx4);
    float xs[4] = {v.x, v.y, v.z, v.w};
    union { __nv_bfloat16 h[4]; uint2 u; } pk[3];
#pragma unroll
    for (int u = 0; u < 4; u++) {
        float x = xs[u];
#pragma unroll
        for (int s = 0; s < 3; s++) {
            __nv_bfloat16 b = __float2bfloat16(x);
            pk[s].h[u] = b;
            x -= __bfloat162float(b);
        }
    }
    int slot0 = si * 3;
    if (isW) {
#pragma unroll
        for (int s = 0; s < 3; s++)
            if (s < NS) *(uint2*)(g_psW[slot0 + s] + idx4) = pk[s].u;
    } else {
#pragma unroll
        for (int s = 0; s < 3; s++)
            if (s < NS) *(uint2*)(g_psA[slot0 + s] + idx4) = pk[s].u;
    }
}

// ---------------- fused q/k/v projection (pre-split operands) ----------------
// q/k results emitted as fp16x2 splits for the eld stage.
__global__ void __launch_bounds__(256, 2) k_proj_all() {
    int z = blockIdx.z;
    int tid = threadIdx.x;
    int wid = tid >> 5, lane = tid & 31;

    unsigned raw = smem_u32(dsmem);
    unsigned sb = (raw + 1023) & ~1023u;
    char* smp = dsmem + (sb - raw);

    float acc[2][8][4];
#pragma unroll
    for (int mi = 0; mi < 2; mi++)
#pragma unroll
        for (int ni = 0; ni < 8; ni++)
#pragma unroll
            for (int u = 0; u < 4; u++) acc[mi][ni][u] = 0.f;

    const __nv_bfloat16* Ab = g_psA[z * 3];
    const __nv_bfloat16* Wb = g_psW[z * 3];
    if (z == 2) {
        gemm_pre<2>(Ab, Wb, sb, smp, acc, 0, 512);
    } else {
        gemm_pre<3>(Ab, Wb, sb, smp, acc, 0, 512);
    }

    __syncthreads();
    float* stage = (float*)smp;
    stage_acc(stage, acc, wid, lane);
    __syncthreads();

    int m0 = blockIdx.y * 128, n0 = blockIdx.x * 128;
    if (z == 2) {
#pragma unroll
        for (int p = 0; p < 16; p++) {
            int f = tid + p * 256;
            int r = f >> 5, q = f & 31;
            int m = m0 + r, bb = m >> 11, l = m & 2047;
            int n = n0 + q * 4, h = n >> 6, dk = n & 63;
            float4 v = *(const float4*)(stage + r * 132 + q * 4);
            *(float4*)(g_vh + ((size_t)(bb * 8 + h) * LSEQ + l) * 64 + dk) = v;
        }
    } else {
        __half* S0 = z ? g_ks[0] : g_qs[0];
        __half* S1 = z ? g_ks[1] : g_qs[1];
#pragma unroll
        for (int p = 0; p < 16; p++) {
            int f = tid + p * 256;
            int r = f >> 5, q = f & 31;
            int m = m0 + r, bb = m >> 11, l = m & 2047;
            int n = n0 + q * 4, h = n >> 6, dk = n & 63;
            float4 v = *(const float4*)(stage + r * 132 + q * 4);
            float xs[4] = {v.x, v.y, v.z, v.w};
            union { __half h4[4]; uint2 u; } p0, p1;
#pragma unroll
            for (int u = 0; u < 4; u++) {
                float x = xs[u];
                __half h0 = __float2half_rn(x);
                float r1 = x - __half2float(h0);
                __half h1 = __float2half_rn(r1);
                p0.h4[u] = h0; p1.h4[u] = h1;
            }
            size_t off = ((size_t)(bb * 8 + h) * LSEQ + l) * 64 + dk;
            *(uint2*)(S0 + off) = p0.u;
            *(uint2*)(S1 + off) = p1.u;
        }
    }
}

// ---------------- fc projection: split-K halves ------------------------------
__global__ void __launch_bounds__(256, 2) k_fc2(const float* __restrict__ wfc) {
    int tid = threadIdx.x;
    int wid = tid >> 5, lane = tid & 31;
    unsigned raw = smem_u32(dsmem);
    unsigned sb = (raw + 1023) & ~1023u;
    char* smp = dsmem + (sb - raw);

    float acc[2][8][4];
#pragma unroll
    for (int mi = 0; mi < 2; mi++)
#pragma unroll
        for (int ni = 0; ni < 8; ni++)
#pragma unroll
            for (int u = 0; u < 4; u++) acc[mi][ni][u] = 0.f;

    int kh = blockIdx.z;   // 0 or 1
    gemm_core<2>(g_attnout, wfc, sb, smp, acc, kh * 256, kh * 256 + 256);

    __syncthreads();
    float* stage = (float*)smp;
    stage_acc(stage, acc, wid, lane);
    __syncthreads();

    float* dst = kh ? g_fcout2 : g_fcout;
    int m0 = blockIdx.y * 128, n0 = blockIdx.x * 128;
#pragma unroll
    for (int p = 0; p < 16; p++) {
        int f = tid + p * 256;
        int r = f >> 5, q = f & 31;
        float4 v = *(const float4*)(stage + r * 132 + q * 4);
        *(float4*)(dst + (size_t)(m0 + r) * 512 + n0 + q * 4) = v;
    }
}

// ---------------- eld logits: fp16x2 HMMA (3 products), direct store ---------
// smem: Q0 @0, K0 @16K, Q1 @32K, K1 @48K
__global__ void __launch_bounds__(256, 2) k_eld_mma() {
    int tid = threadIdx.x;
    int wid = tid >> 5, lane = tid & 31;
    int bh = blockIdx.z;
    int i0 = blockIdx.y * 128, j0 = blockIdx.x * 128;

    unsigned raw = smem_u32(dsmem);
    unsigned sb = (raw + 1023) & ~1023u;

    size_t rbq = ((size_t)bh * LSEQ + i0) * 64;
    size_t rbk = ((size_t)bh * LSEQ + j0) * 64;

#pragma unroll
    for (int g = 0; g < 2; g++) {
        const char* qsrc = (const char*)(g_qs[g] + rbq);
        const char* ksrc = (const char*)(g_ks[g] + rbk);
        unsigned qb = sb + g * 32768;
        unsigned kb2 = sb + 16384 + g * 32768;
#pragma unroll
        for (int p = 0; p < 4; p++) {
            int f = tid + p * 256;
            int r = f >> 3;
            int cb = (f & 7) * 16;
            unsigned off = sw128(r * 128 + cb);
            CP16(qb + off, qsrc + r * 128 + cb);
            CP16(kb2 + off, ksrc + r * 128 + cb);
        }
        CP_COMMIT();
    }

    float acc[2][8][4];
#pragma unroll
    for (int mi = 0; mi < 2; mi++)
#pragma unroll
        for (int ni = 0; ni < 8; ni++)
#pragma unroll
            for (int u = 0; u < 4; u++) acc[mi][ni][u] = 0.f;

    int wr = wid & 3, wc = wid >> 2, sub = lane >> 3, l7 = lane & 7;
    unsigned Q0 = sb, K0 = sb + 16384, Q1 = sb + 32768, K1 = sb + 49152;

    // stage 0: (0,0)
    CP_WAIT(1); __syncthreads();
#pragma unroll
    for (int ks = 0; ks < 4; ks++) {
        int kb = ks * 32;
        unsigned a0[2][4], bfr[8][2];
        ld_afragB(Q0, wr, sub, l7, kb, a0);
        ld_bfragB(K0, wc, sub, l7, kb, bfr);
        mma_allH(acc, a0, bfr);
    }
    // stage 1: (1,0),(0,1)
    CP_WAIT(0); __syncthreads();
#pragma unroll
    for (int ks = 0; ks < 4; ks++) {
        int kb = ks * 32;
        unsigned a0[2][4], a1[2][4], bfr[8][2];
        ld_afragB(Q0, wr, sub, l7, kb, a0);
        ld_afragB(Q1, wr, sub, l7, kb, a1);
        ld_bfragB(K0, wc, sub, l7, kb, bfr);
        mma_allH(acc, a1, bfr);                 // (1,0)
        ld_bfragB(K1, wc, sub, l7, kb, bfr);
        mma_allH(acc, a0, bfr);                 // (0,1)
    }

    // direct epilogue: transform, float2 stores, tilemax atomics
    float* erow = g_eld + ((size_t)bh * LSEQ + i0) * LSEQ + j0;
    int rbase = wr * 32 + (lane >> 2);
    int cbase = wc * 64 + (lane & 3) * 2;
    float mx[2][2] = {{-INFINITY, -INFINITY}, {-INFINITY, -INFINITY}};
#pragma unroll
    for (int mi = 0; mi < 2; mi++) {
#pragma unroll
        for (int hh = 0; hh < 2; hh++) {
            int rloc = rbase + mi * 16 + hh * 8;
            int i = i0 + rloc;
#pragma unroll
            for (int ni = 0; ni < 8; ni++) {
                int cloc = cbase + ni * 8;
                int j = j0 + cloc;
                float e0 = g_dtab[j - i + 2047] * (acc[mi][ni][hh * 2] * 0.125f);
                float e1 = g_dtab[j + 1 - i + 2047] * (acc[mi][ni][hh * 2 + 1] * 0.125f);
                *(float2*)(erow + (size_t)rloc * LSEQ + cloc) = make_float2(e0, e1);
                mx[mi][hh] = fmaxf(mx[mi][hh], fmaxf(e0, e1));
            }
        }
    }
#pragma unroll
    for (int mi = 0; mi < 2; mi++)
#pragma unroll
        for (int hh = 0; hh < 2; hh++) {
            float r = mx[mi][hh];
            r = fmaxf(r, __shfl_xor_sync(0xffffffffu, r, 1));
            r = fmaxf(r, __shfl_xor_sync(0xffffffffu, r, 2));
            if ((lane & 3) == 0) {
                int i = i0 + rbase + mi * 16 + hh * 8;
                unsigned u = __float_as_uint(r);
                unsigned key = (u & 0x80000000u) ? ~u : (u | 0x80000000u);
                atomicMax(&g_tilemax_u[(bh * LSEQ + i) * 16 + blockIdx.x], key);
            }
        }
}

// ---------------- warp-per-row softmax + pool + batched PV ------------------
#define RCAP 128
__global__ void __launch_bounds__(256) k_row6(float* __restrict__ pooled_out) {
    extern __shared__ char rsm[];
    int tid = threadIdx.x, wid = tid >> 5, lane = tid & 31;
    float* p_w = (float*)rsm + wid * 2048;
    unsigned* mC = (unsigned*)(rsm + 65536) + wid * 64;
    unsigned short* cpos_w = (unsigned short*)(rsm + 67584) + wid * RCAP;

    int row = blockIdx.x * 8 + wid;
    int bh = row >> 11;
    int i  = row & 2047;
    int b  = bh >> 3, h = bh & 7;

    float tm = -INFINITY;
    if (lane < 16) {
        unsigned kk = g_tilemax_u[row * 16 + lane];
        unsigned ub = (kk & 0x80000000u) ? (kk ^ 0x80000000u) : ~kk;
        tm = __uint_as_float(ub);
    }
    float mx = tm;
#pragma unroll
    for (int o = 16; o > 0; o >>= 1)
        mx = fmaxf(mx, __shfl_xor_sync(0xffffffffu, mx, o));
    unsigned nd = __ballot_sync(0xffffffffu, tm > mx - 88.0f) & 0xffffu;

    mC[lane] = 0u; mC[lane + 32] = 0u;
    unsigned ti = nd;
    while (ti) {
        int t = __ffs(ti) - 1; ti &= ti - 1;
        *(float4*)(p_w + t * 128 + lane * 4) = make_float4(0.f, 0.f, 0.f, 0.f);
    }
    __syncwarp();

    const float* eldrow = g_eld + (size_t)row * LSEQ;
    float lsum = 0.f;
    ti = nd;
    while (ti) {
        int t = __ffs(ti) - 1; ti &= ti - 1;
        int pos = t * 128 + lane * 4;
        float4 e = *(const float4*)(eldrow + pos);
        float ev[4] = {e.x, e.y, e.z, e.w};
#pragma unroll
        for (int u = 0; u < 4; u++) {
            float arg = ev[u] - mx;
            if (arg > -88.0f) {
                float ex = expf(arg);
                p_w[pos + u] = ex;
                lsum += ex;
                int pp0 = pos + u;
                int lo = (pp0 > 0) ? pp0 - 1 : 0;
                int hi = (pp0 < 2047) ? pp0 + 1 : 2047;
                for (int pp = lo; pp <= hi; pp++)
                    atomicOr(&mC[pp >> 5], 1u << (pp & 31));
            }
        }
    }
    __syncwarp();
#pragma unroll
    for (int o = 16; o > 0; o >>= 1)
        lsum += __shfl_xor_sync(0xffffffffu, lsum, o);
    float S = lsum;

    ti = nd;
    while (ti) {
        int t = __ffs(ti) - 1; ti &= ti - 1;
        int pos = t * 128 + lane * 4;
        float4 pv = *(const float4*)(p_w + pos);
        pv.x /= S; pv.y /= S; pv.z /= S; pv.w /= S;
        *(float4*)(p_w + pos) = pv;
    }
    __syncwarp();

#define PVAL(pos) (((nd >> ((pos) >> 7)) & 1u) ? p_w[(pos)] : 0.f)

    unsigned w0 = mC[lane * 2], w1 = mC[lane * 2 + 1];
    int cnt = __popc(w0) + __popc(w1);
    int incl = cnt;
#pragma unroll
    for (int o = 1; o < 32; o <<= 1) {
        int t = __shfl_up_sync(0xffffffffu, incl, o);
        if (lane >= o) incl += t;
    }
    int basei = incl - cnt;
    int total = __shfl_sync(0xffffffffu, incl, 31);
    {
        int idx = basei;
#pragma unroll
        for (int half = 0; half < 2; half++) {
            unsigned bw = half ? w1 : w0;
            int pbase = lane * 64 + half * 32;
            while (bw) {
                int bp = __ffs((int)bw) - 1;
                bw &= (bw - 1);
                if (idx < RCAP) cpos_w[idx] = (unsigned short)(pbase + bp);
                idx++;
            }
        }
    }
    __syncwarp();
    int cn = (total < RCAP) ? total : RCAP;

    float* prow = pooled_out + (size_t)row * LSEQ;
#pragma unroll 1
    for (int o = 0; o < 16; o++) {
        int pos = o * 128 + lane * 4;
        unsigned bits = (mC[pos >> 5] >> (pos & 31)) & 0xFu;
        float out4[4] = {0.f, 0.f, 0.f, 0.f};
        if (bits) {
#pragma unroll
            for (int u = 0; u < 4; u++) {
                if (bits & (1u << u)) {
                    int p = pos + u;
                    float pm = (p > 0)    ? PVAL(p - 1) : 0.f;
                    float pz = PVAL(p);
                    float pq = (p < 2047) ? PVAL(p + 1) : 0.f;
                    out4[u] = ((pm + pz) + pq) / 3.0f;
                }
            }
        }
        *(float4*)(prow + pos) = make_float4(out4[0], out4[1], out4[2], out4[3]);
    }

    {
        const float* vb = g_vh + (size_t)bh * LSEQ * 64;
        float a0 = 0.f, a1 = 0.f;
#pragma unroll 1
        for (int c0 = 0; c0 < cn; c0 += 8) {
            int nb = cn - c0; if (nb > 8) nb = 8;
            float vl[8], va[8], vq[8];
#pragma unroll
            for (int bq = 0; bq < 8; bq++) {
                if (bq < nb) {
                    int p = cpos_w[c0 + bq];
                    float pm = (p > 0)    ? PVAL(p - 1) : 0.f;
                    float pz = PVAL(p);
                    float pq = (p < 2047) ? PVAL(p + 1) : 0.f;
                    vl[bq] = ((pm + pz) + pq) / 3.0f;
                    const float* vr = vb + (size_t)p * 64;
                    va[bq] = vr[lane];
                    vq[bq] = vr[lane + 32];
                } else { vl[bq] = 0.f; va[bq] = 0.f; vq[bq] = 0.f; }
            }
#pragma unroll
            for (int bq = 0; bq < 8; bq++) {
                a0 = fmaf(vl[bq], va[bq], a0);
                a1 = fmaf(vl[bq], vq[bq], a1);
            }
        }
        float* ob = g_attnout + ((size_t)(b * LSEQ + i)) * DMOD + h * 64;
        ob[lane] = a0;
        ob[lane + 32] = a1;
    }
#undef PVAL
}

// ---------------- residual + LayerNorm (combines fc halves) -----------------
__global__ void k_ln(const float* __restrict__ resid, const float* __restrict__ gamma,
                     const float* __restrict__ beta, float* __restrict__ outp) {
    __shared__ float red[128];
    int m = blockIdx.x;
    int tid = threadIdx.x;
    float4 f0 = *(const float4*)(g_fcout + (size_t)m * 512 + tid * 4);
    float4 f1 = *(const float4*)(g_fcout2 + (size_t)m * 512 + tid * 4);
    float4 r = *(const float4*)(resid + (size_t)m * 512 + tid * 4);
    float y[4] = {(f0.x + f1.x) + r.x, (f0.y + f1.y) + r.y,
                  (f0.z + f1.z) + r.z, (f0.w + f1.w) + r.w};

    float s = (y[0] + y[1]) + (y[2] + y[3]);
    red[tid] = s;
    __syncthreads();
    for (int st = 64; st > 0; st >>= 1) {
        if (tid < st) red[tid] += red[tid + st];
        __syncthreads();
    }
    float mu = red[0] * (1.0f / 512.0f);
    __syncthreads();

    float d[4] = {y[0] - mu, y[1] - mu, y[2] - mu, y[3] - mu};
    float sq = (d[0] * d[0] + d[1] * d[1]) + (d[2] * d[2] + d[3] * d[3]);
    red[tid] = sq;
    __syncthreads();
    for (int st = 64; st > 0; st >>= 1) {
        if (tid < st) red[tid] += red[tid + st];
        __syncthreads();
    }
    float var = red[0] * (1.0f / 512.0f);
    float inv = 1.0f / sqrtf(var + 1e-6f);

    float4 g = *(const float4*)(gamma + tid * 4);
    float4 bb = *(const float4*)(beta + tid * 4);
    float4 o = make_float4(d[0] * inv * g.x + bb.x, d[1] * inv * g.y + bb.y,
                           d[2] * inv * g.z + bb.z, d[3] * inv * g.w + bb.w);
    *(float4*)(outp + (size_t)m * 512 + tid * 4) = o;
}

// ---------------- launch -----------------------------------------------------
#define SMEM3 (98304 + 1024)
#define SMEM2 (67584 + 1024)
#define SMEM_ELD (65536 + 1024)
#define SMEMR (65536 + 2048 + 2048)

extern "C" void kernel_launch(void* const* d_in, const int* in_sizes, int n_in,
                              void* d_out, int out_size) {
    const float* q     = (const float*)d_in[0];
    const float* k     = (const float*)d_in[1];
    const float* v     = (const float*)d_in[2];
    const float* wq    = (const float*)d_in[3];
    const float* wk    = (const float*)d_in[4];
    const float* wv    = (const float*)d_in[5];
    const float* wfc   = (const float*)d_in[6];
    const float* gamma = (const float*)d_in[7];
    const float* beta  = (const float*)d_in[8];

    float* outp = (float*)d_out;            // [B,L,1,D]
    float* pooledp = outp + 2097152;        // [B,H,L,L]

    cudaFuncSetAttribute(k_proj_all, cudaFuncAttributeMaxDynamicSharedMemorySize, SMEM3);
    cudaFuncSetAttribute(k_fc2,      cudaFuncAttributeMaxDynamicSharedMemorySize, SMEM2);
    cudaFuncSetAttribute(k_eld_mma,  cudaFuncAttributeMaxDynamicSharedMemorySize, SMEM_ELD);
    cudaFuncSetAttribute(k_row6,     cudaFuncAttributeMaxDynamicSharedMemorySize, SMEMR);

    k_init<<<2048, 256>>>();
    k_presplit<<<dim3(2048, 1, 6), 256>>>(q, k, v, wq, wk, wv);
    k_proj_all<<<dim3(4, 32, 3), 256, SMEM3>>>();
    k_eld_mma<<<dim3(16, 16, 16), 256, SMEM_ELD>>>();
    k_row6<<<4096, 256, SMEMR>>>(pooledp);
    k_fc2<<<dim3(4, 32, 2), 256, SMEM2>>>(wfc);
    k_ln<<<4096, 128>>>(q, gamma, beta, outp);
}